// round 3
// baseline (speedup 1.0000x reference)
#include <cuda_runtime.h>
#include <math.h>

#define TT 256
#define OBS 512
#define HID 1024
#define MSG 128
#define PED 128

typedef unsigned long long u64;

// ---- device scratch (static; no allocations) ----
__device__ float g_qT[MSG * HID];                 // q transposed: [k][m] 128x1024
__device__ float g_KT[TT * MSG * OBS];            // 64 MB keys transposed: [t][k][i]
__device__ float g_x[TT * OBS];                   // normalized obs
__device__ float g_act[TT * OBS];                 // b_ih+b_hh + W_ih[:,1:]@a_t
__device__ __align__(16) float g_Whh4[512 * 128]; // packed [k/4][j][4]
__device__ __align__(16) float g_Wk4[128 * 128];  // packed [k/4][j][4]
__device__ float g_wih0[512];                     // W_ih[:,0]

// ---- packed fp32x2 helpers (sm_100+) ----
__device__ __forceinline__ u64 pk2(float lo, float hi) {
    u64 r; asm("mov.b64 %0, {%1, %2};" : "=l"(r) : "f"(lo), "f"(hi)); return r;
}
__device__ __forceinline__ u64 dup2(float v) {
    u64 r; asm("mov.b64 %0, {%1, %1};" : "=l"(r) : "f"(v)); return r;
}
__device__ __forceinline__ u64 ffma2(u64 a, u64 b, u64 c) {
    u64 d; asm("fma.rn.f32x2 %0, %1, %2, %3;" : "=l"(d) : "l"(a), "l"(b), "l"(c));
    return d;
}
__device__ __forceinline__ float2 up2(u64 a) {
    float lo, hi; asm("mov.b64 {%0, %1}, %2;" : "=f"(lo), "=f"(hi) : "l"(a));
    return make_float2(lo, hi);
}

__device__ __forceinline__ float fsig(float x) {
    return 1.0f / (1.0f + __expf(-x));
}
__device__ __forceinline__ float ftanh(float x) {
    float t = __expf(-2.0f * fabsf(x));
    float r = (1.0f - t) / (1.0f + t);
    return copysignf(r, x);
}

// ---------------------------------------------------------------------------
// prep: normalize obs, action term, packed weight layouts, wih0
// ---------------------------------------------------------------------------
__global__ void prep_kernel(const float* __restrict__ obs,
                            const float* __restrict__ prev_act,
                            const float* __restrict__ in_shift,
                            const float* __restrict__ in_scale,
                            const float* __restrict__ W_ih,
                            const float* __restrict__ b_ih,
                            const float* __restrict__ W_hh,
                            const float* __restrict__ b_hh,
                            const float* __restrict__ Wk) {
    int idx = blockIdx.x * blockDim.x + threadIdx.x;  // 0..131071
    int i = idx & 511;
    int t = idx >> 9;

    g_x[idx] = (obs[idx] - in_shift[i]) / (in_scale[i] + 1e-8f);

    {   // action term per (t, gate j)
        int j = i;
        float a = b_ih[j] + b_hh[j];
        const float* wr = W_ih + j * 33 + 1;
        const float* ar = prev_act + t * 32;
#pragma unroll
        for (int aa = 0; aa < 32; aa++) a = fmaf(wr[aa], ar[aa], a);
        g_act[idx] = a;
    }

    if (idx < 512 * 128) {  // W_hh [j][k] -> packed [k/4][j][4]
        int j = idx >> 7, k = idx & 127;
        g_Whh4[((k >> 2) * 512 + j) * 4 + (k & 3)] = W_hh[idx];
    }
    if (idx < 128 * 128) {  // Wk [j][k] -> packed [k/4][j][4]
        int j = idx >> 7, k = idx & 127;
        g_Wk4[((k >> 2) * 128 + j) * 4 + (k & 3)] = Wk[idx];
    }
    if (idx < 512) g_wih0[idx] = W_ih[idx * 33];
}

// ---------------------------------------------------------------------------
// qT[k][m] = (pos_embedding @ Wq^T + bq)^T
// ---------------------------------------------------------------------------
__global__ void q_kernel(const float* __restrict__ pe,
                         const float* __restrict__ Wq,
                         const float* __restrict__ bq) {
    int idx = blockIdx.x * blockDim.x + threadIdx.x;  // 131072
    int m = idx >> 7, j = idx & 127;
    float acc = bq[j];
    const float* per = pe + m * 128;
    const float* wr = Wq + j * 128;
#pragma unroll 4
    for (int k = 0; k < 128; k++) acc = fmaf(per[k], wr[k], acc);
    g_qT[j * 1024 + m] = acc;
}

// ---------------------------------------------------------------------------
// Phase A: 512 independent LSTM chains. 128 CTAs x 4 neurons, 512 threads.
// f32x2 packed gate GEMM; Wk + 25% of Whh resident in smem.
// Writes keys transposed to g_KT[t][k][i].
// ---------------------------------------------------------------------------
#define LSTM_SMEM ((16384 + 16384 + 2048 + 512*5 + 128 + 4) * (int)sizeof(float))

__global__ __launch_bounds__(512) void lstm_kernel(const float* __restrict__ bk) {
    extern __shared__ float sm[];
    float* Wk_s   = sm;               // 16384 : packed [k/4][j][4]
    float* Whh_s  = Wk_s + 16384;     // 16384 : packed first 8 k4-chunks [k4][j][4]
    float* gt_s   = Whh_s + 16384;    // 2048  : [n][512]
    float* h4_s   = gt_s + 2048;      // 512   : [k][n] interleaved
    float* h_s    = h4_s + 512;       // 512   : [n][k]
    float* c_s    = h_s + 512;        // 512
    float* act_s  = c_s + 512;        // 512
    float* wih0_s = act_s + 512;      // 512
    float* bk_s   = wih0_s + 512;     // 128
    float* s_s    = bk_s + 128;       // 4

    int tid = threadIdx.x;            // 0..511
    int n0 = blockIdx.x * 4;

    // one-time staging
    {
        const float4* src = (const float4*)g_Wk4;
        float4* dst = (float4*)Wk_s;
#pragma unroll
        for (int f = 0; f < 8; f++) dst[tid + f * 512] = src[tid + f * 512];
        const float4* src2 = (const float4*)g_Whh4;  // first 8 k4 chunks = 4096 float4
        float4* dst2 = (float4*)Whh_s;
#pragma unroll
        for (int f = 0; f < 8; f++) dst2[tid + f * 512] = src2[tid + f * 512];
    }
    h4_s[tid] = 0.0f;
    h_s[tid] = 0.0f;
    c_s[tid] = 0.0f;
    wih0_s[tid] = g_wih0[tid];
    if (tid < 128) bk_s[tid] = bk[tid];
    __syncthreads();

    const float4* Whh = (const float4*)g_Whh4;  // [k4*512 + j]
    int j = tid;

    for (int t = 0; t < TT; t++) {
        act_s[j] = g_act[t * 512 + j];
        if (tid < 4) s_s[tid] = g_x[t * 512 + n0 + tid];
        __syncthreads();

        // ---- gate GEMM (packed over neuron pairs) ----
        u64 p01, p23;
        {
            float aj = act_s[j], wj = wih0_s[j];
            p01 = pk2(fmaf(s_s[0], wj, aj), fmaf(s_s[1], wj, aj));
            p23 = pk2(fmaf(s_s[2], wj, aj), fmaf(s_s[3], wj, aj));
        }
#pragma unroll 4
        for (int k4 = 0; k4 < 8; k4++) {   // smem-resident W slice
            float4 w = *(const float4*)&Whh_s[(k4 * 512 + j) * 4];
            float wa[4] = {w.x, w.y, w.z, w.w};
#pragma unroll
            for (int d = 0; d < 4; d++) {
                float4 h4 = *(const float4*)&h4_s[(k4 * 4 + d) * 4];
                u64 wd = dup2(wa[d]);
                p01 = ffma2(wd, pk2(h4.x, h4.y), p01);
                p23 = ffma2(wd, pk2(h4.z, h4.w), p23);
            }
        }
#pragma unroll 4
        for (int k4 = 8; k4 < 32; k4++) {  // streamed from L2
            float4 w = Whh[k4 * 512 + j];
            float wa[4] = {w.x, w.y, w.z, w.w};
#pragma unroll
            for (int d = 0; d < 4; d++) {
                float4 h4 = *(const float4*)&h4_s[(k4 * 4 + d) * 4];
                u64 wd = dup2(wa[d]);
                p01 = ffma2(wd, pk2(h4.x, h4.y), p01);
                p23 = ffma2(wd, pk2(h4.z, h4.w), p23);
            }
        }
        {
            float2 v01 = up2(p01), v23 = up2(p23);
            gt_s[0 * 512 + j] = v01.x;
            gt_s[1 * 512 + j] = v01.y;
            gt_s[2 * 512 + j] = v23.x;
            gt_s[3 * 512 + j] = v23.y;
        }
        __syncthreads();

        // ---- LSTM pointwise (torch gate order i,f,g,o) ----
        {
            int n = tid >> 7, jj = tid & 127;
            float ig = gt_s[n * 512 + jj];
            float fg = gt_s[n * 512 + 128 + jj];
            float gg = gt_s[n * 512 + 256 + jj];
            float og = gt_s[n * 512 + 384 + jj];
            float c = fsig(fg) * c_s[tid] + fsig(ig) * ftanh(gg);
            float h = fsig(og) * ftanh(c);
            c_s[tid] = c;
            h_s[n * 128 + jj] = h;
            h4_s[jj * 4 + n] = h;
        }
        __syncthreads();

        // ---- key message: K[t][jj][n0+n] = h[n] . Wk[jj] + bk[jj] (transposed out)
        {
            int n = tid >> 7, jj = tid & 127;
            u64 accp = pk2(bk_s[jj], 0.0f);
#pragma unroll 4
            for (int k4 = 0; k4 < 32; k4++) {
                float4 w = *(const float4*)&Wk_s[(k4 * 128 + jj) * 4];
                float4 hv = *(const float4*)&h_s[n * 128 + k4 * 4];
                accp = ffma2(pk2(w.x, w.y), pk2(hv.x, hv.y), accp);
                accp = ffma2(pk2(w.z, w.w), pk2(hv.z, hv.w), accp);
            }
            float2 v = up2(accp);
            g_KT[t * 65536 + jj * 512 + n0 + n] = v.x + v.y;
        }
        __syncthreads();
    }
}

// ---------------------------------------------------------------------------
// Phase B: out[t,m] = tanh( sum_i tanh((q[m].K[t,i])/sqrt(128)) * s[t,i] )
// f32x2 packed over i-pairs; qT/KT tiles in smem (transposed layouts).
// ---------------------------------------------------------------------------
#define ATTN_SMEM ((16384 + 16384 + 512) * (int)sizeof(float))

__global__ __launch_bounds__(256) void attn_kernel(float* __restrict__ out) {
    extern __shared__ float sm[];
    float* qT_s = sm;              // [k][m'] 128x128
    float* KT_s = sm + 16384;      // [k][i'] 128x128
    float* s_s  = sm + 32768;      // 512

    int tid = threadIdx.x;
    int mt = blockIdx.x;  // 0..7
    int t  = blockIdx.y;  // 0..255
    int mh = tid >> 4;    // 0..15
    int ih = tid & 15;    // 0..15

    // load qT tile [k][mt*128 + m'] (coalesced rows)
    for (int f = tid; f < 128 * 32; f += 256) {
        int k = f >> 5, m4 = f & 31;
        *(float4*)&qT_s[k * 128 + m4 * 4] =
            *(const float4*)&g_qT[k * 1024 + mt * 128 + m4 * 4];
    }
    for (int idx = tid; idx < 512; idx += 256) s_s[idx] = g_x[t * 512 + idx];

    float outa[8] = {0, 0, 0, 0, 0, 0, 0, 0};
    const float inv = 0.0883883476483184f;  // 1/sqrt(128)

    for (int c = 0; c < 4; c++) {
        __syncthreads();
        for (int f = tid; f < 128 * 32; f += 256) {
            int k = f >> 5, i4 = f & 31;
            *(float4*)&KT_s[k * 128 + i4 * 4] =
                *(const float4*)&g_KT[t * 65536 + k * 512 + c * 128 + i4 * 4];
        }
        __syncthreads();

        u64 acc[8][4];
#pragma unroll
        for (int a = 0; a < 8; a++)
#pragma unroll
            for (int p = 0; p < 4; p++) acc[a][p] = 0ull;

#pragma unroll 2
        for (int k = 0; k < 128; k++) {
            float4 ka = *(const float4*)&KT_s[k * 128 + ih * 4];
            float4 kb = *(const float4*)&KT_s[k * 128 + 64 + ih * 4];
            u64 kp0 = pk2(ka.x, ka.y), kp1 = pk2(ka.z, ka.w);
            u64 kp2 = pk2(kb.x, kb.y), kp3 = pk2(kb.z, kb.w);
            float4 qa = *(const float4*)&qT_s[k * 128 + mh * 4];
            float4 qb = *(const float4*)&qT_s[k * 128 + 64 + mh * 4];
            float qs[8] = {qa.x, qa.y, qa.z, qa.w, qb.x, qb.y, qb.z, qb.w};
#pragma unroll
            for (int a = 0; a < 8; a++) {
                u64 qd = dup2(qs[a]);
                acc[a][0] = ffma2(qd, kp0, acc[a][0]);
                acc[a][1] = ffma2(qd, kp1, acc[a][1]);
                acc[a][2] = ffma2(qd, kp2, acc[a][2]);
                acc[a][3] = ffma2(qd, kp3, acc[a][3]);
            }
        }

        // epilogue: tanh + weight by s
        int ibase = c * 128;
#pragma unroll
        for (int p = 0; p < 4; p++) {
            int i0 = ibase + ((p < 2) ? (ih * 4 + p * 2) : (64 + ih * 4 + (p - 2) * 2));
            float sv0 = s_s[i0], sv1 = s_s[i0 + 1];
#pragma unroll
            for (int a = 0; a < 8; a++) {
                float2 v = up2(acc[a][p]);
                outa[a] = fmaf(ftanh(v.x * inv), sv0, outa[a]);
                outa[a] = fmaf(ftanh(v.y * inv), sv1, outa[a]);
            }
        }
    }

    // reduce over the 16 ih-lanes
#pragma unroll
    for (int a = 0; a < 8; a++) {
        float v = outa[a];
        v += __shfl_xor_sync(0xffffffffu, v, 1);
        v += __shfl_xor_sync(0xffffffffu, v, 2);
        v += __shfl_xor_sync(0xffffffffu, v, 4);
        v += __shfl_xor_sync(0xffffffffu, v, 8);
        if (ih == 0) {
            int mp = (a < 4) ? (mh * 4 + a) : (64 + mh * 4 + (a - 4));
            out[t * 1024 + mt * 128 + mp] = ftanh(v);
        }
    }
}

// ---------------------------------------------------------------------------
extern "C" void kernel_launch(void* const* d_in, const int* in_sizes, int n_in,
                              void* d_out, int out_size) {
    const float* obs      = (const float*)d_in[0];
    const float* prev_act = (const float*)d_in[1];
    const float* in_shift = (const float*)d_in[2];
    const float* in_scale = (const float*)d_in[3];
    const float* pe       = (const float*)d_in[4];
    const float* W_ih     = (const float*)d_in[5];
    const float* b_ih     = (const float*)d_in[6];
    const float* W_hh     = (const float*)d_in[7];
    const float* b_hh     = (const float*)d_in[8];
    const float* Wq       = (const float*)d_in[9];
    const float* bq       = (const float*)d_in[10];
    const float* Wk       = (const float*)d_in[11];
    const float* bk       = (const float*)d_in[12];
    float* out = (float*)d_out;

    cudaFuncSetAttribute(attn_kernel, cudaFuncAttributeMaxDynamicSharedMemorySize,
                         ATTN_SMEM);
    cudaFuncSetAttribute(lstm_kernel, cudaFuncAttributeMaxDynamicSharedMemorySize,
                         LSTM_SMEM);

    prep_kernel<<<512, 256>>>(obs, prev_act, in_shift, in_scale,
                              W_ih, b_ih, W_hh, b_hh, Wk);
    q_kernel<<<512, 256>>>(pe, Wq, bq);
    lstm_kernel<<<128, 512, LSTM_SMEM>>>(bk);
    dim3 ga(8, 256);
    attn_kernel<<<ga, 256, ATTN_SMEM>>>(out);
}

// round 5
// speedup vs baseline: 1.4469x; 1.4469x over previous
#include <cuda_runtime.h>
#include <cuda_bf16.h>
#include <math.h>
#include <stdint.h>

#define TT 256
#define OBS 512
#define HID 1024
#define MSG 128

typedef unsigned long long u64;

// ---- device scratch (static; no allocations) ----
__device__ __align__(16) __nv_bfloat16 g_qh[HID * MSG];        // q hi  [m][k]
__device__ __align__(16) __nv_bfloat16 g_ql[HID * MSG];        // q lo
__device__ __align__(16) __nv_bfloat16 g_Kh[TT * OBS * MSG];   // K hi  [t][i][k]
__device__ __align__(16) __nv_bfloat16 g_Kl[TT * OBS * MSG];   // K lo
__device__ float g_x[TT * OBS];                                // normalized obs
__device__ float g_act[TT * OBS];                              // b_ih+b_hh + W_ih[:,1:]@a_t
__device__ __align__(16) float g_Whh4[512 * 128];              // packed [k/4][j][4]
__device__ __align__(16) float g_Wk4[128 * 128];               // packed [k/4][j][4]
__device__ float g_wih0[512];                                  // W_ih[:,0]

// ---- packed fp32x2 helpers ----
__device__ __forceinline__ u64 pk2(float lo, float hi) {
    u64 r; asm("mov.b64 %0, {%1, %2};" : "=l"(r) : "f"(lo), "f"(hi)); return r;
}
__device__ __forceinline__ u64 dup2(float v) {
    u64 r; asm("mov.b64 %0, {%1, %1};" : "=l"(r) : "f"(v)); return r;
}
__device__ __forceinline__ u64 ffma2(u64 a, u64 b, u64 c) {
    u64 d; asm("fma.rn.f32x2 %0, %1, %2, %3;" : "=l"(d) : "l"(a), "l"(b), "l"(c));
    return d;
}
__device__ __forceinline__ float2 up2(u64 a) {
    float lo, hi; asm("mov.b64 {%0, %1}, %2;" : "=f"(lo), "=f"(hi) : "l"(a));
    return make_float2(lo, hi);
}

__device__ __forceinline__ float fsig(float x) {
    return 1.0f / (1.0f + __expf(-x));
}
__device__ __forceinline__ float ftanh(float x) {
    float t = __expf(-2.0f * fabsf(x));
    float r = (1.0f - t) / (1.0f + t);
    return copysignf(r, x);
}

// ---------------------------------------------------------------------------
// prep: normalize obs, action term, packed weight layouts, wih0
// ---------------------------------------------------------------------------
__global__ void prep_kernel(const float* __restrict__ obs,
                            const float* __restrict__ prev_act,
                            const float* __restrict__ in_shift,
                            const float* __restrict__ in_scale,
                            const float* __restrict__ W_ih,
                            const float* __restrict__ b_ih,
                            const float* __restrict__ W_hh,
                            const float* __restrict__ b_hh,
                            const float* __restrict__ Wk) {
    int idx = blockIdx.x * blockDim.x + threadIdx.x;  // 0..131071
    int i = idx & 511;
    int t = idx >> 9;

    g_x[idx] = (obs[idx] - in_shift[i]) / (in_scale[i] + 1e-8f);

    {   // action term per (t, gate j)
        int j = i;
        float a = b_ih[j] + b_hh[j];
        const float* wr = W_ih + j * 33 + 1;
        const float* ar = prev_act + t * 32;
#pragma unroll
        for (int aa = 0; aa < 32; aa++) a = fmaf(wr[aa], ar[aa], a);
        g_act[idx] = a;
    }

    if (idx < 512 * 128) {  // W_hh [j][k] -> packed [k/4][j][4]
        int j = idx >> 7, k = idx & 127;
        g_Whh4[((k >> 2) * 512 + j) * 4 + (k & 3)] = W_hh[idx];
    }
    if (idx < 128 * 128) {  // Wk [j][k] -> packed [k/4][j][4]
        int j = idx >> 7, k = idx & 127;
        g_Wk4[((k >> 2) * 128 + j) * 4 + (k & 3)] = Wk[idx];
    }
    if (idx < 512) g_wih0[idx] = W_ih[idx * 33];
}

// ---------------------------------------------------------------------------
// q = pos_embedding @ Wq^T + bq, stored as bf16 hi/lo pairs [m][k]
// ---------------------------------------------------------------------------
__global__ void q_kernel(const float* __restrict__ pe,
                         const float* __restrict__ Wq,
                         const float* __restrict__ bq) {
    int idx = blockIdx.x * blockDim.x + threadIdx.x;  // 131072
    int m = idx >> 7, j = idx & 127;
    float acc = bq[j];
    const float* per = pe + m * 128;
    const float* wr = Wq + j * 128;
#pragma unroll 4
    for (int k = 0; k < 128; k++) acc = fmaf(per[k], wr[k], acc);

    __nv_bfloat16 hb = __float2bfloat16(acc);
    __nv_bfloat16 lb = __float2bfloat16(acc - __bfloat162float(hb));
    g_qh[idx] = hb;
    g_ql[idx] = lb;
}

// ---------------------------------------------------------------------------
// Phase A: 512 independent LSTM chains. 128 CTAs x 4 neurons, 512 threads.
// W_hh: 16 k4-chunks in smem + 16 in registers (no steady-state L2 W stream).
// Emits keys as bf16 hi/lo pairs [t][i][k].
// ---------------------------------------------------------------------------
#define LSTM_SMEM ((16384 + 32768 + 2048 + 512 * 5 + 128 + 4) * (int)sizeof(float))

__global__ __launch_bounds__(512) void lstm_kernel(const float* __restrict__ bk) {
    extern __shared__ float sm[];
    float* Wk_s   = sm;               // 16384 : packed [k/4][j][4]
    float* Whh_s  = Wk_s + 16384;     // 32768 : packed k4-chunks 0..15 [k4][j][4]
    float* gt_s   = Whh_s + 32768;    // 2048  : [n][512]
    float* h4_s   = gt_s + 2048;      // 512   : [k][n] interleaved
    float* h_s    = h4_s + 512;       // 512   : [n][k]
    float* c_s    = h_s + 512;        // 512
    float* act_s  = c_s + 512;        // 512
    float* wih0_s = act_s + 512;      // 512
    float* bk_s   = wih0_s + 512;     // 128
    float* s_s    = bk_s + 128;       // 4

    int tid = threadIdx.x;            // 0..511
    int n0 = blockIdx.x * 4;
    int j = tid;

    // one-time staging
    {
        const float4* src = (const float4*)g_Wk4;
        float4* dst = (float4*)Wk_s;
#pragma unroll
        for (int f = 0; f < 8; f++) dst[tid + f * 512] = src[tid + f * 512];
        const float4* src2 = (const float4*)g_Whh4;  // chunks 0..15 = 8192 float4
        float4* dst2 = (float4*)Whh_s;
#pragma unroll
        for (int f = 0; f < 16; f++) dst2[tid + f * 512] = src2[tid + f * 512];
    }
    // register-resident W_hh chunks 16..31 (this thread's column j)
    float4 wreg[16];
    {
        const float4* Whh = (const float4*)g_Whh4;
#pragma unroll
        for (int c = 0; c < 16; c++) wreg[c] = Whh[(16 + c) * 512 + j];
    }
    h4_s[tid] = 0.0f;
    h_s[tid] = 0.0f;
    c_s[tid] = 0.0f;
    wih0_s[tid] = g_wih0[tid];
    if (tid < 128) bk_s[tid] = bk[tid];
    __syncthreads();

    for (int t = 0; t < TT; t++) {
        act_s[j] = g_act[t * 512 + j];
        if (tid < 4) s_s[tid] = g_x[t * 512 + n0 + tid];
        __syncthreads();

        // ---- gate GEMM (packed over neuron pairs) ----
        u64 p01, p23;
        {
            float aj = act_s[j], wj = wih0_s[j];
            p01 = pk2(fmaf(s_s[0], wj, aj), fmaf(s_s[1], wj, aj));
            p23 = pk2(fmaf(s_s[2], wj, aj), fmaf(s_s[3], wj, aj));
        }
#pragma unroll 4
        for (int k4 = 0; k4 < 16; k4++) {   // smem-resident half
            float4 w = *(const float4*)&Whh_s[(k4 * 512 + j) * 4];
            float wa[4] = {w.x, w.y, w.z, w.w};
#pragma unroll
            for (int d = 0; d < 4; d++) {
                float4 h4 = *(const float4*)&h4_s[(k4 * 4 + d) * 4];
                u64 wd = dup2(wa[d]);
                p01 = ffma2(wd, pk2(h4.x, h4.y), p01);
                p23 = ffma2(wd, pk2(h4.z, h4.w), p23);
            }
        }
#pragma unroll
        for (int k4 = 16; k4 < 32; k4++) {  // register-resident half
            float4 w = wreg[k4 - 16];
            float wa[4] = {w.x, w.y, w.z, w.w};
#pragma unroll
            for (int d = 0; d < 4; d++) {
                float4 h4 = *(const float4*)&h4_s[(k4 * 4 + d) * 4];
                u64 wd = dup2(wa[d]);
                p01 = ffma2(wd, pk2(h4.x, h4.y), p01);
                p23 = ffma2(wd, pk2(h4.z, h4.w), p23);
            }
        }
        {
            float2 v01 = up2(p01), v23 = up2(p23);
            gt_s[0 * 512 + j] = v01.x;
            gt_s[1 * 512 + j] = v01.y;
            gt_s[2 * 512 + j] = v23.x;
            gt_s[3 * 512 + j] = v23.y;
        }
        __syncthreads();

        // ---- LSTM pointwise (torch gate order i,f,g,o) ----
        {
            int n = tid >> 7, jj = tid & 127;
            float ig = gt_s[n * 512 + jj];
            float fg = gt_s[n * 512 + 128 + jj];
            float gg = gt_s[n * 512 + 256 + jj];
            float og = gt_s[n * 512 + 384 + jj];
            float c = fsig(fg) * c_s[tid] + fsig(ig) * ftanh(gg);
            float h = fsig(og) * ftanh(c);
            c_s[tid] = c;
            h_s[n * 128 + jj] = h;
            h4_s[jj * 4 + n] = h;
        }
        __syncthreads();

        // ---- key message: acc = h[n] . Wk[jj] + bk[jj]; bf16 hi/lo store
        {
            int n = tid >> 7, jj = tid & 127;
            u64 accp = pk2(bk_s[jj], 0.0f);
#pragma unroll 4
            for (int k4 = 0; k4 < 32; k4++) {
                float4 w = *(const float4*)&Wk_s[(k4 * 128 + jj) * 4];
                float4 hv = *(const float4*)&h_s[n * 128 + k4 * 4];
                accp = ffma2(pk2(w.x, w.y), pk2(hv.x, hv.y), accp);
                accp = ffma2(pk2(w.z, w.w), pk2(hv.z, hv.w), accp);
            }
            float2 v = up2(accp);
            float acc = v.x + v.y;
            __nv_bfloat16 hb = __float2bfloat16(acc);
            __nv_bfloat16 lb = __float2bfloat16(acc - __bfloat162float(hb));
            size_t off = (size_t)t * 65536 + (size_t)(n0 + n) * 128 + jj;
            g_Kh[off] = hb;
            g_Kl[off] = lb;
        }
        __syncthreads();
    }
}

// ---------------------------------------------------------------------------
// Phase B via mma.sync m16n8k16 bf16 (hi/lo split, fp32 accumulate).
// CTA (mt, t): 128 m x 512 i, k = 128. 8 warps x 16 m rows each, all 512 i.
// out[t,m] = tanh( sum_i tanh(score/sqrt(128)) * s[t,i] )
// ---------------------------------------------------------------------------
#define QP 136   // smem row pitch (bf16) -> conflict-free 32-bit fragment loads
#define TILE_E (128 * QP)
#define ATTN_SMEM (4 * TILE_E * 2 + 512 * 4 + 256)

__device__ __forceinline__ uint32_t lds_u32(const __nv_bfloat16* p) {
    return *(const uint32_t*)p;
}

__device__ __forceinline__ void mma_bf16(float* d, const uint32_t* a,
                                         uint32_t b0, uint32_t b1) {
    asm volatile(
        "mma.sync.aligned.m16n8k16.row.col.f32.bf16.bf16.f32 "
        "{%0,%1,%2,%3}, {%4,%5,%6,%7}, {%8,%9}, {%0,%1,%2,%3};"
        : "+f"(d[0]), "+f"(d[1]), "+f"(d[2]), "+f"(d[3])
        : "r"(a[0]), "r"(a[1]), "r"(a[2]), "r"(a[3]), "r"(b0), "r"(b1));
}

__global__ __launch_bounds__(256) void attn_kernel(float* __restrict__ out) {
    extern __shared__ char smc[];
    __nv_bfloat16* qh_s = (__nv_bfloat16*)smc;        // 128 x QP
    __nv_bfloat16* ql_s = qh_s + TILE_E;
    __nv_bfloat16* Kh_s = ql_s + TILE_E;
    __nv_bfloat16* Kl_s = Kh_s + TILE_E;
    float* s_s = (float*)(Kl_s + TILE_E);             // 512 floats

    int tid = threadIdx.x;
    int warp = tid >> 5;
    int lane = tid & 31;
    int g  = lane >> 2;     // groupID 0..7
    int tg = lane & 3;      // thread-in-group
    int m0 = warp * 16;
    int mt = blockIdx.x;    // 0..7
    int t  = blockIdx.y;    // 0..255

    // stage q tile (hi/lo) with pitch QP
    {
        const float4* sh = (const float4*)&g_qh[(size_t)mt * 128 * 128];
        const float4* sl = (const float4*)&g_ql[(size_t)mt * 128 * 128];
        for (int f = tid; f < 2048; f += 256) {
            int row = f >> 4, qd = f & 15;
            *(float4*)&qh_s[row * QP + qd * 8] = sh[f];
            *(float4*)&ql_s[row * QP + qd * 8] = sl[f];
        }
        const float4* sx = (const float4*)&g_x[t * 512];
        if (tid < 128) ((float4*)s_s)[tid] = sx[tid];
    }

    float pr0 = 0.0f, pr1 = 0.0f;   // partials for rows m0+g, m0+g+8
    const float inv = 0.0883883476483184f;  // 1/sqrt(128)

#pragma unroll 1
    for (int c = 0; c < 4; c++) {
        if (c > 0) __syncthreads();   // everyone done with previous K tile
        {
            const float4* sh = (const float4*)&g_Kh[(size_t)t * 65536 + (size_t)c * 128 * 128];
            const float4* sl = (const float4*)&g_Kl[(size_t)t * 65536 + (size_t)c * 128 * 128];
            for (int f = tid; f < 2048; f += 256) {
                int row = f >> 4, qd = f & 15;
                *(float4*)&Kh_s[row * QP + qd * 8] = sh[f];
                *(float4*)&Kl_s[row * QP + qd * 8] = sl[f];
            }
        }
        __syncthreads();

        float acc[16][4];
#pragma unroll
        for (int nt = 0; nt < 16; nt++)
#pragma unroll
            for (int e = 0; e < 4; e++) acc[nt][e] = 0.0f;

#pragma unroll 1
        for (int kk = 0; kk < 8; kk++) {
            int ka = kk * 16 + tg * 2;
            uint32_t ah[4], al[4];
            ah[0] = lds_u32(&qh_s[(m0 + g) * QP + ka]);
            ah[1] = lds_u32(&qh_s[(m0 + g + 8) * QP + ka]);
            ah[2] = lds_u32(&qh_s[(m0 + g) * QP + ka + 8]);
            ah[3] = lds_u32(&qh_s[(m0 + g + 8) * QP + ka + 8]);
            al[0] = lds_u32(&ql_s[(m0 + g) * QP + ka]);
            al[1] = lds_u32(&ql_s[(m0 + g + 8) * QP + ka]);
            al[2] = lds_u32(&ql_s[(m0 + g) * QP + ka + 8]);
            al[3] = lds_u32(&ql_s[(m0 + g + 8) * QP + ka + 8]);
#pragma unroll
            for (int nt = 0; nt < 16; nt++) {
                int ib = (nt * 8 + g) * QP + ka;
                uint32_t bh0 = lds_u32(&Kh_s[ib]);
                uint32_t bh1 = lds_u32(&Kh_s[ib + 8]);
                uint32_t bl0 = lds_u32(&Kl_s[ib]);
                uint32_t bl1 = lds_u32(&Kl_s[ib + 8]);
                mma_bf16(acc[nt], ah, bh0, bh1);   // hi*hi
                mma_bf16(acc[nt], ah, bl0, bl1);   // hi*lo
                mma_bf16(acc[nt], al, bh0, bh1);   // lo*hi
            }
        }

        // epilogue for this chunk: tanh(score*inv) * s[i]
#pragma unroll
        for (int nt = 0; nt < 16; nt++) {
            int i0 = c * 128 + nt * 8 + tg * 2;
            float sv0 = s_s[i0], sv1 = s_s[i0 + 1];
            pr0 = fmaf(ftanh(acc[nt][0] * inv), sv0, pr0);
            pr0 = fmaf(ftanh(acc[nt][1] * inv), sv1, pr0);
            pr1 = fmaf(ftanh(acc[nt][2] * inv), sv0, pr1);
            pr1 = fmaf(ftanh(acc[nt][3] * inv), sv1, pr1);
        }
    }

    // reduce over the 4 tg lanes that share the same rows
    pr0 += __shfl_xor_sync(0xffffffffu, pr0, 1);
    pr0 += __shfl_xor_sync(0xffffffffu, pr0, 2);
    pr1 += __shfl_xor_sync(0xffffffffu, pr1, 1);
    pr1 += __shfl_xor_sync(0xffffffffu, pr1, 2);
    if (tg == 0) {
        out[t * 1024 + mt * 128 + m0 + g]     = ftanh(pr0);
        out[t * 1024 + mt * 128 + m0 + g + 8] = ftanh(pr1);
    }
}

// ---------------------------------------------------------------------------
extern "C" void kernel_launch(void* const* d_in, const int* in_sizes, int n_in,
                              void* d_out, int out_size) {
    const float* obs      = (const float*)d_in[0];
    const float* prev_act = (const float*)d_in[1];
    const float* in_shift = (const float*)d_in[2];
    const float* in_scale = (const float*)d_in[3];
    const float* pe       = (const float*)d_in[4];
    const float* W_ih     = (const float*)d_in[5];
    const float* b_ih     = (const float*)d_in[6];
    const float* W_hh     = (const float*)d_in[7];
    const float* b_hh     = (const float*)d_in[8];
    const float* Wq       = (const float*)d_in[9];
    const float* bq       = (const float*)d_in[10];
    const float* Wk       = (const float*)d_in[11];
    const float* bk       = (const float*)d_in[12];
    float* out = (float*)d_out;

    cudaFuncSetAttribute(attn_kernel, cudaFuncAttributeMaxDynamicSharedMemorySize,
                         ATTN_SMEM);
    cudaFuncSetAttribute(lstm_kernel, cudaFuncAttributeMaxDynamicSharedMemorySize,
                         LSTM_SMEM);

    prep_kernel<<<512, 256>>>(obs, prev_act, in_shift, in_scale,
                              W_ih, b_ih, W_hh, b_hh, Wk);
    q_kernel<<<512, 256>>>(pe, Wq, bq);
    lstm_kernel<<<128, 512, LSTM_SMEM>>>(bk);
    dim3 ga(8, 256);
    attn_kernel<<<ga, 256, ATTN_SMEM>>>(out);
}

// round 6
// speedup vs baseline: 1.6050x; 1.1093x over previous
#include <cuda_runtime.h>
#include <cuda_bf16.h>
#include <math.h>
#include <stdint.h>

#define TT 256
#define OBS 512
#define HID 1024
#define MSG 128

typedef unsigned long long u64;

// ---- device scratch (static; no allocations) ----
__device__ __align__(16) __nv_bfloat16 g_qh[HID * MSG];        // q hi  [m][k]
__device__ __align__(16) __nv_bfloat16 g_ql[HID * MSG];        // q lo
__device__ __align__(16) __nv_bfloat16 g_Kh[TT * OBS * MSG];   // K hi  [t][i][k]
__device__ __align__(16) __nv_bfloat16 g_Kl[TT * OBS * MSG];   // K lo
__device__ float g_x[TT * OBS];                                // normalized obs
__device__ float g_act[TT * OBS];                              // b_ih+b_hh + W_ih[:,1:]@a_t
__device__ float g_wih0[512];                                  // W_ih[:,0]

// ---- packed fp32x2 helpers ----
__device__ __forceinline__ u64 ffma2(u64 a, u64 b, u64 c) {
    u64 d; asm("fma.rn.f32x2 %0, %1, %2, %3;" : "=l"(d) : "l"(a), "l"(b), "l"(c));
    return d;
}
__device__ __forceinline__ float2 up2(u64 a) {
    float lo, hi; asm("mov.b64 {%0, %1}, %2;" : "=f"(lo), "=f"(hi) : "l"(a));
    return make_float2(lo, hi);
}

__device__ __forceinline__ float fsig(float x) {
    return 1.0f / (1.0f + __expf(-x));
}
__device__ __forceinline__ float ftanh(float x) {
    float t = __expf(-2.0f * fabsf(x));
    float r = (1.0f - t) / (1.0f + t);
    return copysignf(r, x);
}

// ---------------------------------------------------------------------------
// prep: normalize obs, action term, wih0
// ---------------------------------------------------------------------------
__global__ void prep_kernel(const float* __restrict__ obs,
                            const float* __restrict__ prev_act,
                            const float* __restrict__ in_shift,
                            const float* __restrict__ in_scale,
                            const float* __restrict__ W_ih,
                            const float* __restrict__ b_ih,
                            const float* __restrict__ b_hh) {
    int idx = blockIdx.x * blockDim.x + threadIdx.x;  // 0..131071
    int i = idx & 511;
    int t = idx >> 9;

    g_x[idx] = (obs[idx] - in_shift[i]) / (in_scale[i] + 1e-8f);

    {   // action term per (t, gate j)
        int j = i;
        float a = b_ih[j] + b_hh[j];
        const float* wr = W_ih + j * 33 + 1;
        const float* ar = prev_act + t * 32;
#pragma unroll
        for (int aa = 0; aa < 32; aa++) a = fmaf(wr[aa], ar[aa], a);
        g_act[idx] = a;
    }
    if (idx < 512) g_wih0[idx] = W_ih[idx * 33];
}

// ---------------------------------------------------------------------------
// q = pos_embedding @ Wq^T + bq, stored as bf16 hi/lo pairs [m][k]
// ---------------------------------------------------------------------------
__global__ void q_kernel(const float* __restrict__ pe,
                         const float* __restrict__ Wq,
                         const float* __restrict__ bq) {
    int idx = blockIdx.x * blockDim.x + threadIdx.x;  // 131072
    int m = idx >> 7, j = idx & 127;
    float acc = bq[j];
    const float* per = pe + m * 128;
    const float* wr = Wq + j * 128;
#pragma unroll 4
    for (int k = 0; k < 128; k++) acc = fmaf(per[k], wr[k], acc);

    __nv_bfloat16 hb = __float2bfloat16(acc);
    __nv_bfloat16 lb = __float2bfloat16(acc - __bfloat162float(hb));
    g_qh[idx] = hb;
    g_ql[idx] = lb;
}

// ---------------------------------------------------------------------------
// Phase A: 512 independent LSTM chains. 128 CTAs x 4 neurons, 512 threads.
// k-pair f32x2 packing: zero pack MOVs. W_hh: k<64 smem / k>=64 registers.
// kmsg split (jj x k-quarter) + reduce to avoid Wk crossbar duplication.
// ---------------------------------------------------------------------------
#define WHH_P 68
#define WK_P 132
#define LSTM_SMEM ((512 * WHH_P + 128 * WK_P + 2048 + 2048 + 512 + 8) * (int)sizeof(float))

__global__ __launch_bounds__(512) void lstm_kernel(const float* __restrict__ W_hh,
                                                   const float* __restrict__ Wk,
                                                   const float* __restrict__ bk) {
    extern __shared__ float sm[];
    float* Whh_s = sm;                         // 512 x WHH_P (k 0..63)
    float* Wk_s  = Whh_s + 512 * WHH_P;        // 128 x WK_P
    float* gt_s  = Wk_s + 128 * WK_P;          // 2048 : [n][512]
    float* kp_s  = gt_s + 2048;                // 2048 : [ks][n][128]
    float* h_s   = kp_s + 2048;                // 512  : [n][128]
    float* s_s   = h_s + 512;                  // 8    : double-buffered s

    int tid = threadIdx.x;                     // 0..511
    int n0 = blockIdx.x * 4;
    int j = tid;

    // --- one-time staging ---
    {   // Whh rows, k 0..63, pitch WHH_P (phase-conflict-free LDS.128)
        const float4* wr = (const float4*)(W_hh + j * 128);
#pragma unroll
        for (int i = 0; i < 16; i++)
            *(float4*)&Whh_s[j * WHH_P + i * 4] = wr[i];
    }
    ulonglong2 wreg[16];   // Whh row j, k 64..127 (register-resident)
    {
        const ulonglong2* wr = (const ulonglong2*)(W_hh + j * 128 + 64);
#pragma unroll
        for (int i = 0; i < 16; i++) wreg[i] = wr[i];
    }
    for (int f = tid; f < 128 * 32; f += 512) {   // Wk rows, pitch WK_P
        int row = f >> 5, q4 = f & 31;
        *(float4*)&Wk_s[row * WK_P + q4 * 4] = *(const float4*)&Wk[row * 128 + q4 * 4];
    }
    h_s[tid] = 0.0f;
    float c_r    = 0.0f;
    float act_r  = g_act[j];
    float wih0_r = g_wih0[j];
    float bk_r   = bk[tid & 127];
    if (tid < 4) s_s[tid] = g_x[n0 + tid];
    __syncthreads();

    for (int t = 0; t < TT; t++) {
        const float* sb = s_s + (t & 1) * 4;

        // ---- gate GEMM: thread = column j, 4 neurons, k-pair packed ----
        u64 a0 = 0, a1 = 0, a2 = 0, a3 = 0;
#pragma unroll
        for (int k4 = 0; k4 < 16; k4++) {   // smem W half
            ulonglong2 wv = *(const ulonglong2*)&Whh_s[j * WHH_P + k4 * 4];
            ulonglong2 h0 = *(const ulonglong2*)&h_s[k4 * 4];
            ulonglong2 h1 = *(const ulonglong2*)&h_s[128 + k4 * 4];
            ulonglong2 h2 = *(const ulonglong2*)&h_s[256 + k4 * 4];
            ulonglong2 h3 = *(const ulonglong2*)&h_s[384 + k4 * 4];
            a0 = ffma2(wv.x, h0.x, a0); a0 = ffma2(wv.y, h0.y, a0);
            a1 = ffma2(wv.x, h1.x, a1); a1 = ffma2(wv.y, h1.y, a1);
            a2 = ffma2(wv.x, h2.x, a2); a2 = ffma2(wv.y, h2.y, a2);
            a3 = ffma2(wv.x, h3.x, a3); a3 = ffma2(wv.y, h3.y, a3);
        }
#pragma unroll
        for (int k4 = 16; k4 < 32; k4++) {  // register W half
            ulonglong2 wv = wreg[k4 - 16];
            ulonglong2 h0 = *(const ulonglong2*)&h_s[k4 * 4];
            ulonglong2 h1 = *(const ulonglong2*)&h_s[128 + k4 * 4];
            ulonglong2 h2 = *(const ulonglong2*)&h_s[256 + k4 * 4];
            ulonglong2 h3 = *(const ulonglong2*)&h_s[384 + k4 * 4];
            a0 = ffma2(wv.x, h0.x, a0); a0 = ffma2(wv.y, h0.y, a0);
            a1 = ffma2(wv.x, h1.x, a1); a1 = ffma2(wv.y, h1.y, a1);
            a2 = ffma2(wv.x, h2.x, a2); a2 = ffma2(wv.y, h2.y, a2);
            a3 = ffma2(wv.x, h3.x, a3); a3 = ffma2(wv.y, h3.y, a3);
        }
        {
            float base = act_r;
            float2 v0 = up2(a0), v1 = up2(a1), v2 = up2(a2), v3 = up2(a3);
            gt_s[0 * 512 + j] = v0.x + v0.y + fmaf(sb[0], wih0_r, base);
            gt_s[1 * 512 + j] = v1.x + v1.y + fmaf(sb[1], wih0_r, base);
            gt_s[2 * 512 + j] = v2.x + v2.y + fmaf(sb[2], wih0_r, base);
            gt_s[3 * 512 + j] = v3.x + v3.y + fmaf(sb[3], wih0_r, base);
        }
        __syncthreads();

        // ---- LSTM pointwise (torch gate order i,f,g,o); c in register ----
        {
            int n = tid >> 7, jj = tid & 127;
            float ig = gt_s[n * 512 + jj];
            float fg = gt_s[n * 512 + 128 + jj];
            float gg = gt_s[n * 512 + 256 + jj];
            float og = gt_s[n * 512 + 384 + jj];
            float c = fsig(fg) * c_r + fsig(ig) * ftanh(gg);
            float h = fsig(og) * ftanh(c);
            c_r = c;
            h_s[n * 128 + jj] = h;
        }
        {
            int tn = (t + 1 < TT) ? t + 1 : t;
            if (tid < 4) s_s[((t + 1) & 1) * 4 + tid] = g_x[tn * 512 + n0 + tid];
            act_r = g_act[tn * 512 + j];
        }
        __syncthreads();

        // ---- kmsg partial: thread = (ks = tid>>7 k-quarter, jj = tid&127) ----
        {
            int ks = tid >> 7, jj = tid & 127;
            u64 ka0 = 0, ka1 = 0, ka2 = 0, ka3 = 0;
#pragma unroll
            for (int k4i = 0; k4i < 8; k4i++) {
                int k4 = ks * 8 + k4i;
                ulonglong2 wv = *(const ulonglong2*)&Wk_s[jj * WK_P + k4 * 4];
                ulonglong2 h0 = *(const ulonglong2*)&h_s[k4 * 4];
                ulonglong2 h1 = *(const ulonglong2*)&h_s[128 + k4 * 4];
                ulonglong2 h2 = *(const ulonglong2*)&h_s[256 + k4 * 4];
                ulonglong2 h3 = *(const ulonglong2*)&h_s[384 + k4 * 4];
                ka0 = ffma2(wv.x, h0.x, ka0); ka0 = ffma2(wv.y, h0.y, ka0);
                ka1 = ffma2(wv.x, h1.x, ka1); ka1 = ffma2(wv.y, h1.y, ka1);
                ka2 = ffma2(wv.x, h2.x, ka2); ka2 = ffma2(wv.y, h2.y, ka2);
                ka3 = ffma2(wv.x, h3.x, ka3); ka3 = ffma2(wv.y, h3.y, ka3);
            }
            float2 v0 = up2(ka0), v1 = up2(ka1), v2 = up2(ka2), v3 = up2(ka3);
            kp_s[ks * 512 + 0 * 128 + jj] = v0.x + v0.y;
            kp_s[ks * 512 + 1 * 128 + jj] = v1.x + v1.y;
            kp_s[ks * 512 + 2 * 128 + jj] = v2.x + v2.y;
            kp_s[ks * 512 + 3 * 128 + jj] = v3.x + v3.y;
        }
        __syncthreads();

        // ---- reduce 4 partials, bf16 hi/lo store ----
        {
            int n = tid >> 7, jj = tid & 127;
            float acc = bk_r
                      + kp_s[n * 128 + jj]        + kp_s[512 + n * 128 + jj]
                      + kp_s[1024 + n * 128 + jj] + kp_s[1536 + n * 128 + jj];
            __nv_bfloat16 hb = __float2bfloat16(acc);
            __nv_bfloat16 lb = __float2bfloat16(acc - __bfloat162float(hb));
            size_t off = (size_t)t * 65536 + (size_t)(n0 + n) * 128 + jj;
            g_Kh[off] = hb;
            g_Kl[off] = lb;
        }
        // no barrier needed: next gates touch gt_s/h_s only, both stable
    }
}

// ---------------------------------------------------------------------------
// Phase B via mma.sync m16n8k16 bf16 (hi/lo split, fp32 accumulate).
// CTA (mt, t): 128 m x 512 i, k = 128. 8 warps x 16 m rows each, all 512 i.
// out[t,m] = tanh( sum_i tanh(score/sqrt(128)) * s[t,i] )
// ---------------------------------------------------------------------------
#define QP 136   // smem row pitch (bf16) -> conflict-free 32-bit fragment loads
#define TILE_E (128 * QP)
#define ATTN_SMEM (4 * TILE_E * 2 + 512 * 4 + 256)

__device__ __forceinline__ uint32_t lds_u32(const __nv_bfloat16* p) {
    return *(const uint32_t*)p;
}

__device__ __forceinline__ void mma_bf16(float* d, const uint32_t* a,
                                         uint32_t b0, uint32_t b1) {
    asm volatile(
        "mma.sync.aligned.m16n8k16.row.col.f32.bf16.bf16.f32 "
        "{%0,%1,%2,%3}, {%4,%5,%6,%7}, {%8,%9}, {%0,%1,%2,%3};"
        : "+f"(d[0]), "+f"(d[1]), "+f"(d[2]), "+f"(d[3])
        : "r"(a[0]), "r"(a[1]), "r"(a[2]), "r"(a[3]), "r"(b0), "r"(b1));
}

__global__ __launch_bounds__(256) void attn_kernel(float* __restrict__ out) {
    extern __shared__ char smc[];
    __nv_bfloat16* qh_s = (__nv_bfloat16*)smc;        // 128 x QP
    __nv_bfloat16* ql_s = qh_s + TILE_E;
    __nv_bfloat16* Kh_s = ql_s + TILE_E;
    __nv_bfloat16* Kl_s = Kh_s + TILE_E;
    float* s_s = (float*)(Kl_s + TILE_E);             // 512 floats

    int tid = threadIdx.x;
    int warp = tid >> 5;
    int lane = tid & 31;
    int g  = lane >> 2;     // groupID 0..7
    int tg = lane & 3;      // thread-in-group
    int m0 = warp * 16;
    int mt = blockIdx.x;    // 0..7
    int t  = blockIdx.y;    // 0..255

    // stage q tile (hi/lo) with pitch QP
    {
        const float4* sh = (const float4*)&g_qh[(size_t)mt * 128 * 128];
        const float4* sl = (const float4*)&g_ql[(size_t)mt * 128 * 128];
        for (int f = tid; f < 2048; f += 256) {
            int row = f >> 4, qd = f & 15;
            *(float4*)&qh_s[row * QP + qd * 8] = sh[f];
            *(float4*)&ql_s[row * QP + qd * 8] = sl[f];
        }
        const float4* sx = (const float4*)&g_x[t * 512];
        if (tid < 128) ((float4*)s_s)[tid] = sx[tid];
    }

    float pr0 = 0.0f, pr1 = 0.0f;   // partials for rows m0+g, m0+g+8
    const float inv = 0.0883883476483184f;  // 1/sqrt(128)

#pragma unroll 1
    for (int c = 0; c < 4; c++) {
        if (c > 0) __syncthreads();   // everyone done with previous K tile
        {
            const float4* sh = (const float4*)&g_Kh[(size_t)t * 65536 + (size_t)c * 128 * 128];
            const float4* sl = (const float4*)&g_Kl[(size_t)t * 65536 + (size_t)c * 128 * 128];
            for (int f = tid; f < 2048; f += 256) {
                int row = f >> 4, qd = f & 15;
                *(float4*)&Kh_s[row * QP + qd * 8] = sh[f];
                *(float4*)&Kl_s[row * QP + qd * 8] = sl[f];
            }
        }
        __syncthreads();

        float acc[16][4];
#pragma unroll
        for (int nt = 0; nt < 16; nt++)
#pragma unroll
            for (int e = 0; e < 4; e++) acc[nt][e] = 0.0f;

#pragma unroll 1
        for (int kk = 0; kk < 8; kk++) {
            int ka = kk * 16 + tg * 2;
            uint32_t ah[4], al[4];
            ah[0] = lds_u32(&qh_s[(m0 + g) * QP + ka]);
            ah[1] = lds_u32(&qh_s[(m0 + g + 8) * QP + ka]);
            ah[2] = lds_u32(&qh_s[(m0 + g) * QP + ka + 8]);
            ah[3] = lds_u32(&qh_s[(m0 + g + 8) * QP + ka + 8]);
            al[0] = lds_u32(&ql_s[(m0 + g) * QP + ka]);
            al[1] = lds_u32(&ql_s[(m0 + g + 8) * QP + ka]);
            al[2] = lds_u32(&ql_s[(m0 + g) * QP + ka + 8]);
            al[3] = lds_u32(&ql_s[(m0 + g + 8) * QP + ka + 8]);
#pragma unroll
            for (int nt = 0; nt < 16; nt++) {
                int ib = (nt * 8 + g) * QP + ka;
                uint32_t bh0 = lds_u32(&Kh_s[ib]);
                uint32_t bh1 = lds_u32(&Kh_s[ib + 8]);
                uint32_t bl0 = lds_u32(&Kl_s[ib]);
                uint32_t bl1 = lds_u32(&Kl_s[ib + 8]);
                mma_bf16(acc[nt], ah, bh0, bh1);   // hi*hi
                mma_bf16(acc[nt], ah, bl0, bl1);   // hi*lo
                mma_bf16(acc[nt], al, bh0, bh1);   // lo*hi
            }
        }

        // epilogue for this chunk: tanh(score*inv) * s[i]
#pragma unroll
        for (int nt = 0; nt < 16; nt++) {
            int i0 = c * 128 + nt * 8 + tg * 2;
            float sv0 = s_s[i0], sv1 = s_s[i0 + 1];
            pr0 = fmaf(ftanh(acc[nt][0] * inv), sv0, pr0);
            pr0 = fmaf(ftanh(acc[nt][1] * inv), sv1, pr0);
            pr1 = fmaf(ftanh(acc[nt][2] * inv), sv0, pr1);
            pr1 = fmaf(ftanh(acc[nt][3] * inv), sv1, pr1);
        }
    }

    // reduce over the 4 tg lanes that share the same rows
    pr0 += __shfl_xor_sync(0xffffffffu, pr0, 1);
    pr0 += __shfl_xor_sync(0xffffffffu, pr0, 2);
    pr1 += __shfl_xor_sync(0xffffffffu, pr1, 1);
    pr1 += __shfl_xor_sync(0xffffffffu, pr1, 2);
    if (tg == 0) {
        out[t * 1024 + mt * 128 + m0 + g]     = ftanh(pr0);
        out[t * 1024 + mt * 128 + m0 + g + 8] = ftanh(pr1);
    }
}

// ---------------------------------------------------------------------------
extern "C" void kernel_launch(void* const* d_in, const int* in_sizes, int n_in,
                              void* d_out, int out_size) {
    const float* obs      = (const float*)d_in[0];
    const float* prev_act = (const float*)d_in[1];
    const float* in_shift = (const float*)d_in[2];
    const float* in_scale = (const float*)d_in[3];
    const float* pe       = (const float*)d_in[4];
    const float* W_ih     = (const float*)d_in[5];
    const float* b_ih     = (const float*)d_in[6];
    const float* W_hh     = (const float*)d_in[7];
    const float* b_hh     = (const float*)d_in[8];
    const float* Wq       = (const float*)d_in[9];
    const float* bq       = (const float*)d_in[10];
    const float* Wk       = (const float*)d_in[11];
    const float* bk       = (const float*)d_in[12];
    float* out = (float*)d_out;

    cudaFuncSetAttribute(attn_kernel, cudaFuncAttributeMaxDynamicSharedMemorySize,
                         ATTN_SMEM);
    cudaFuncSetAttribute(lstm_kernel, cudaFuncAttributeMaxDynamicSharedMemorySize,
                         LSTM_SMEM);

    prep_kernel<<<512, 256>>>(obs, prev_act, in_shift, in_scale, W_ih, b_ih, b_hh);
    q_kernel<<<512, 256>>>(pe, Wq, bq);
    lstm_kernel<<<128, 512, LSTM_SMEM>>>(W_hh, Wk, bk);
    dim3 ga(8, 256);
    attn_kernel<<<ga, 256, ATTN_SMEM>>>(out);
}

// round 7
// speedup vs baseline: 1.6793x; 1.0463x over previous
#include <cuda_runtime.h>
#include <cuda_bf16.h>
#include <math.h>
#include <stdint.h>

#define TT 256
#define OBS 512
#define HID 1024
#define MSG 128

typedef unsigned long long u64;

// ---- device scratch (static; no allocations) ----
__device__ __align__(16) __nv_bfloat16 g_qh[HID * MSG];        // q hi  [m][k]
__device__ __align__(16) __nv_bfloat16 g_ql[HID * MSG];        // q lo
__device__ __align__(16) __nv_bfloat16 g_Kh[TT * OBS * MSG];   // K hi  [t][i][k]
__device__ __align__(16) __nv_bfloat16 g_Kl[TT * OBS * MSG];   // K lo
__device__ float g_x[TT * OBS];                                // normalized obs
__device__ float g_act[TT * OBS];                              // b_ih+b_hh + W_ih[:,1:]@a_t
__device__ float g_wih0[512];                                  // W_ih[:,0]

// ---- packed fp32x2 helpers ----
__device__ __forceinline__ u64 ffma2(u64 a, u64 b, u64 c) {
    u64 d; asm("fma.rn.f32x2 %0, %1, %2, %3;" : "=l"(d) : "l"(a), "l"(b), "l"(c));
    return d;
}
__device__ __forceinline__ float2 up2(u64 a) {
    float lo, hi; asm("mov.b64 {%0, %1}, %2;" : "=f"(lo), "=f"(hi) : "l"(a));
    return make_float2(lo, hi);
}

__device__ __forceinline__ float fsig(float x) {
    return 1.0f / (1.0f + __expf(-x));
}
__device__ __forceinline__ float ftanh(float x) {
    float t = __expf(-2.0f * fabsf(x));
    float r = (1.0f - t) / (1.0f + t);
    return copysignf(r, x);
}

// ---------------------------------------------------------------------------
// prep: normalize obs, action term, wih0
// ---------------------------------------------------------------------------
__global__ void prep_kernel(const float* __restrict__ obs,
                            const float* __restrict__ prev_act,
                            const float* __restrict__ in_shift,
                            const float* __restrict__ in_scale,
                            const float* __restrict__ W_ih,
                            const float* __restrict__ b_ih,
                            const float* __restrict__ b_hh) {
    int idx = blockIdx.x * blockDim.x + threadIdx.x;  // 0..131071
    int i = idx & 511;
    int t = idx >> 9;

    g_x[idx] = (obs[idx] - in_shift[i]) / (in_scale[i] + 1e-8f);

    {   // action term per (t, gate j)
        int j = i;
        float a = b_ih[j] + b_hh[j];
        const float* wr = W_ih + j * 33 + 1;
        const float* ar = prev_act + t * 32;
#pragma unroll
        for (int aa = 0; aa < 32; aa++) a = fmaf(wr[aa], ar[aa], a);
        g_act[idx] = a;
    }
    if (idx < 512) g_wih0[idx] = W_ih[idx * 33];
}

// ---------------------------------------------------------------------------
// q = pos_embedding @ Wq^T + bq, stored as bf16 hi/lo pairs [m][k]
// ---------------------------------------------------------------------------
__global__ void q_kernel(const float* __restrict__ pe,
                         const float* __restrict__ Wq,
                         const float* __restrict__ bq) {
    int idx = blockIdx.x * blockDim.x + threadIdx.x;  // 131072
    int m = idx >> 7, j = idx & 127;
    float acc = bq[j];
    const float* per = pe + m * 128;
    const float* wr = Wq + j * 128;
#pragma unroll 4
    for (int k = 0; k < 128; k++) acc = fmaf(per[k], wr[k], acc);

    __nv_bfloat16 hb = __float2bfloat16(acc);
    __nv_bfloat16 lb = __float2bfloat16(acc - __bfloat162float(hb));
    g_qh[idx] = hb;
    g_ql[idx] = lb;
}

// ---------------------------------------------------------------------------
// Phase A/B fused LSTM: 128 CTAs x 4 neurons, 512 threads, 2 barriers/step.
// Phase A: gates(t) [h(t-1)] AND kmsg-partials(t-1) [same h(t-1)] — two
// independent instruction streams for ILP. Phase B: pointwise(t) +
// kmsg reduce/store(t-1) + prefetch.
// ---------------------------------------------------------------------------
#define WHH_P 68
#define WK_P 132
#define LSTM_SMEM ((512 * WHH_P + 128 * WK_P + 2048 + 2048 + 512 + 8) * (int)sizeof(float))

__global__ __launch_bounds__(512) void lstm_kernel(const float* __restrict__ W_hh,
                                                   const float* __restrict__ Wk,
                                                   const float* __restrict__ bk) {
    extern __shared__ float sm[];
    float* Whh_s = sm;                         // 512 x WHH_P (k 0..63)
    float* Wk_s  = Whh_s + 512 * WHH_P;        // 128 x WK_P
    float* gt_s  = Wk_s + 128 * WK_P;          // 2048 : [n][512]
    float* kp_s  = gt_s + 2048;                // 2048 : [ks][n][128]
    float* h_s   = kp_s + 2048;                // 512  : [n][128]
    float* s_s   = h_s + 512;                  // 8    : double-buffered s

    int tid = threadIdx.x;                     // 0..511
    int n0 = blockIdx.x * 4;
    int j = tid;
    int ks = tid >> 7, jj = tid & 127;         // kmsg / pointwise mapping

    // --- one-time staging ---
    {   // Whh rows, k 0..63, pitch WHH_P
        const float4* wr = (const float4*)(W_hh + j * 128);
#pragma unroll
        for (int i = 0; i < 16; i++)
            *(float4*)&Whh_s[j * WHH_P + i * 4] = wr[i];
    }
    ulonglong2 wreg[16];   // Whh row j, k 64..127 (register-resident)
    {
        const ulonglong2* wr = (const ulonglong2*)(W_hh + j * 128 + 64);
#pragma unroll
        for (int i = 0; i < 16; i++) wreg[i] = wr[i];
    }
    for (int f = tid; f < 128 * 32; f += 512) {   // Wk rows, pitch WK_P
        int row = f >> 5, q4 = f & 31;
        *(float4*)&Wk_s[row * WK_P + q4 * 4] = *(const float4*)&Wk[row * 128 + q4 * 4];
    }
    h_s[tid] = 0.0f;
    float c_r    = 0.0f;
    float act_r  = g_act[j];
    float wih0_r = g_wih0[j];
    float bk_r   = bk[jj];
    if (tid < 4) s_s[tid] = g_x[n0 + tid];
    __syncthreads();

    for (int t = 0; t < TT; t++) {
        const float* sb = s_s + (t & 1) * 4;

        // ================= Phase A =================
        // gates(t): thread = column j, 4 neurons, k-pair packed
        u64 a0 = 0, a1 = 0, a2 = 0, a3 = 0;
#pragma unroll
        for (int k4 = 0; k4 < 16; k4++) {   // smem W half
            ulonglong2 wv = *(const ulonglong2*)&Whh_s[j * WHH_P + k4 * 4];
            ulonglong2 h0 = *(const ulonglong2*)&h_s[k4 * 4];
            ulonglong2 h1 = *(const ulonglong2*)&h_s[128 + k4 * 4];
            ulonglong2 h2 = *(const ulonglong2*)&h_s[256 + k4 * 4];
            ulonglong2 h3 = *(const ulonglong2*)&h_s[384 + k4 * 4];
            a0 = ffma2(wv.x, h0.x, a0); a0 = ffma2(wv.y, h0.y, a0);
            a1 = ffma2(wv.x, h1.x, a1); a1 = ffma2(wv.y, h1.y, a1);
            a2 = ffma2(wv.x, h2.x, a2); a2 = ffma2(wv.y, h2.y, a2);
            a3 = ffma2(wv.x, h3.x, a3); a3 = ffma2(wv.y, h3.y, a3);
        }
#pragma unroll
        for (int k4 = 16; k4 < 32; k4++) {  // register W half
            ulonglong2 wv = wreg[k4 - 16];
            ulonglong2 h0 = *(const ulonglong2*)&h_s[k4 * 4];
            ulonglong2 h1 = *(const ulonglong2*)&h_s[128 + k4 * 4];
            ulonglong2 h2 = *(const ulonglong2*)&h_s[256 + k4 * 4];
            ulonglong2 h3 = *(const ulonglong2*)&h_s[384 + k4 * 4];
            a0 = ffma2(wv.x, h0.x, a0); a0 = ffma2(wv.y, h0.y, a0);
            a1 = ffma2(wv.x, h1.x, a1); a1 = ffma2(wv.y, h1.y, a1);
            a2 = ffma2(wv.x, h2.x, a2); a2 = ffma2(wv.y, h2.y, a2);
            a3 = ffma2(wv.x, h3.x, a3); a3 = ffma2(wv.y, h3.y, a3);
        }
        {
            float base = act_r;
            float2 v0 = up2(a0), v1 = up2(a1), v2 = up2(a2), v3 = up2(a3);
            gt_s[0 * 512 + j] = v0.x + v0.y + fmaf(sb[0], wih0_r, base);
            gt_s[1 * 512 + j] = v1.x + v1.y + fmaf(sb[1], wih0_r, base);
            gt_s[2 * 512 + j] = v2.x + v2.y + fmaf(sb[2], wih0_r, base);
            gt_s[3 * 512 + j] = v3.x + v3.y + fmaf(sb[3], wih0_r, base);
        }
        // kmsg partials for step t-1 (h_s still holds h(t-1))
        if (t > 0) {
            u64 ka0 = 0, ka1 = 0, ka2 = 0, ka3 = 0;
#pragma unroll
            for (int k4i = 0; k4i < 8; k4i++) {
                int k4 = ks * 8 + k4i;
                ulonglong2 wv = *(const ulonglong2*)&Wk_s[jj * WK_P + k4 * 4];
                ulonglong2 h0 = *(const ulonglong2*)&h_s[k4 * 4];
                ulonglong2 h1 = *(const ulonglong2*)&h_s[128 + k4 * 4];
                ulonglong2 h2 = *(const ulonglong2*)&h_s[256 + k4 * 4];
                ulonglong2 h3 = *(const ulonglong2*)&h_s[384 + k4 * 4];
                ka0 = ffma2(wv.x, h0.x, ka0); ka0 = ffma2(wv.y, h0.y, ka0);
                ka1 = ffma2(wv.x, h1.x, ka1); ka1 = ffma2(wv.y, h1.y, ka1);
                ka2 = ffma2(wv.x, h2.x, ka2); ka2 = ffma2(wv.y, h2.y, ka2);
                ka3 = ffma2(wv.x, h3.x, ka3); ka3 = ffma2(wv.y, h3.y, ka3);
            }
            float2 v0 = up2(ka0), v1 = up2(ka1), v2 = up2(ka2), v3 = up2(ka3);
            kp_s[ks * 512 + 0 * 128 + jj] = v0.x + v0.y;
            kp_s[ks * 512 + 1 * 128 + jj] = v1.x + v1.y;
            kp_s[ks * 512 + 2 * 128 + jj] = v2.x + v2.y;
            kp_s[ks * 512 + 3 * 128 + jj] = v3.x + v3.y;
        }
        __syncthreads();

        // ================= Phase B =================
        // kmsg reduce + store for step t-1
        if (t > 0) {
            float acc = bk_r
                      + kp_s[ks * 128 + jj]        + kp_s[512 + ks * 128 + jj]
                      + kp_s[1024 + ks * 128 + jj] + kp_s[1536 + ks * 128 + jj];
            // NOTE: here ks doubles as the neuron index n (both tid>>7)
            __nv_bfloat16 hb = __float2bfloat16(acc);
            __nv_bfloat16 lb = __float2bfloat16(acc - __bfloat162float(hb));
            size_t off = (size_t)(t - 1) * 65536 + (size_t)(n0 + ks) * 128 + jj;
            g_Kh[off] = hb;
            g_Kl[off] = lb;
        }
        // pointwise(t): gt_s -> h_s (torch gate order i,f,g,o); c in register
        {
            float ig = gt_s[ks * 512 + jj];
            float fg = gt_s[ks * 512 + 128 + jj];
            float gg = gt_s[ks * 512 + 256 + jj];
            float og = gt_s[ks * 512 + 384 + jj];
            float c = fsig(fg) * c_r + fsig(ig) * ftanh(gg);
            float h = fsig(og) * ftanh(c);
            c_r = c;
            h_s[ks * 128 + jj] = h;
        }
        // prefetch next-step inputs
        {
            int tn = (t + 1 < TT) ? t + 1 : t;
            if (tid < 4) s_s[((t + 1) & 1) * 4 + tid] = g_x[tn * 512 + n0 + tid];
            act_r = g_act[tn * 512 + j];
        }
        __syncthreads();
    }

    // ---- tail: kmsg for step 255 (h_s holds h(255)) ----
    {
        u64 ka0 = 0, ka1 = 0, ka2 = 0, ka3 = 0;
#pragma unroll
        for (int k4i = 0; k4i < 8; k4i++) {
            int k4 = ks * 8 + k4i;
            ulonglong2 wv = *(const ulonglong2*)&Wk_s[jj * WK_P + k4 * 4];
            ulonglong2 h0 = *(const ulonglong2*)&h_s[k4 * 4];
            ulonglong2 h1 = *(const ulonglong2*)&h_s[128 + k4 * 4];
            ulonglong2 h2 = *(const ulonglong2*)&h_s[256 + k4 * 4];
            ulonglong2 h3 = *(const ulonglong2*)&h_s[384 + k4 * 4];
            ka0 = ffma2(wv.x, h0.x, ka0); ka0 = ffma2(wv.y, h0.y, ka0);
            ka1 = ffma2(wv.x, h1.x, ka1); ka1 = ffma2(wv.y, h1.y, ka1);
            ka2 = ffma2(wv.x, h2.x, ka2); ka2 = ffma2(wv.y, h2.y, ka2);
            ka3 = ffma2(wv.x, h3.x, ka3); ka3 = ffma2(wv.y, h3.y, ka3);
        }
        float2 v0 = up2(ka0), v1 = up2(ka1), v2 = up2(ka2), v3 = up2(ka3);
        kp_s[ks * 512 + 0 * 128 + jj] = v0.x + v0.y;
        kp_s[ks * 512 + 1 * 128 + jj] = v1.x + v1.y;
        kp_s[ks * 512 + 2 * 128 + jj] = v2.x + v2.y;
        kp_s[ks * 512 + 3 * 128 + jj] = v3.x + v3.y;
    }
    __syncthreads();
    {
        float acc = bk_r
                  + kp_s[ks * 128 + jj]        + kp_s[512 + ks * 128 + jj]
                  + kp_s[1024 + ks * 128 + jj] + kp_s[1536 + ks * 128 + jj];
        __nv_bfloat16 hb = __float2bfloat16(acc);
        __nv_bfloat16 lb = __float2bfloat16(acc - __bfloat162float(hb));
        size_t off = (size_t)255 * 65536 + (size_t)(n0 + ks) * 128 + jj;
        g_Kh[off] = hb;
        g_Kl[off] = lb;
    }
}

// ---------------------------------------------------------------------------
// Phase B via mma.sync m16n8k16 bf16 (hi/lo split, fp32 accumulate).
// 512 threads: warp = (m-band 0..7, i-half 0..1). Each warp: 16 m rows,
// 64 i per chunk. Partials combined via smem.
// ---------------------------------------------------------------------------
#define QP 136   // smem row pitch (bf16) -> conflict-free 32-bit fragment loads
#define TILE_E (128 * QP)
#define ATTN_SMEM (4 * TILE_E * 2 + 512 * 4 + 256 * 4 + 128)

__device__ __forceinline__ uint32_t lds_u32(const __nv_bfloat16* p) {
    return *(const uint32_t*)p;
}

__device__ __forceinline__ void mma_bf16(float* d, const uint32_t* a,
                                         uint32_t b0, uint32_t b1) {
    asm volatile(
        "mma.sync.aligned.m16n8k16.row.col.f32.bf16.bf16.f32 "
        "{%0,%1,%2,%3}, {%4,%5,%6,%7}, {%8,%9}, {%0,%1,%2,%3};"
        : "+f"(d[0]), "+f"(d[1]), "+f"(d[2]), "+f"(d[3])
        : "r"(a[0]), "r"(a[1]), "r"(a[2]), "r"(a[3]), "r"(b0), "r"(b1));
}

__global__ __launch_bounds__(512) void attn_kernel(float* __restrict__ out) {
    extern __shared__ char smc[];
    __nv_bfloat16* qh_s = (__nv_bfloat16*)smc;        // 128 x QP
    __nv_bfloat16* ql_s = qh_s + TILE_E;
    __nv_bfloat16* Kh_s = ql_s + TILE_E;
    __nv_bfloat16* Kl_s = Kh_s + TILE_E;
    float* s_s  = (float*)(Kl_s + TILE_E);            // 512 floats
    float* part = s_s + 512;                          // 256 floats

    int tid = threadIdx.x;
    int warp = tid >> 5;
    int lane = tid & 31;
    int wband = warp >> 1;   // 0..7 : m band (16 rows)
    int ihalf = warp & 1;    // 0..1 : i half within chunk
    int g  = lane >> 2;      // 0..7
    int tg = lane & 3;       // 0..3
    int m0 = wband * 16;
    int mt = blockIdx.x;     // 0..7
    int t  = blockIdx.y;     // 0..255

    // stage q tile (hi/lo) with pitch QP
    {
        const float4* sh = (const float4*)&g_qh[(size_t)mt * 128 * 128];
        const float4* sl = (const float4*)&g_ql[(size_t)mt * 128 * 128];
        for (int f = tid; f < 2048; f += 512) {
            int row = f >> 4, qd = f & 15;
            *(float4*)&qh_s[row * QP + qd * 8] = sh[f];
            *(float4*)&ql_s[row * QP + qd * 8] = sl[f];
        }
        const float4* sx = (const float4*)&g_x[t * 512];
        if (tid < 128) ((float4*)s_s)[tid] = sx[tid];
    }

    float pr0 = 0.0f, pr1 = 0.0f;   // partials for rows m0+g, m0+g+8
    const float inv = 0.0883883476483184f;  // 1/sqrt(128)

#pragma unroll 1
    for (int c = 0; c < 4; c++) {
        if (c > 0) __syncthreads();   // everyone done with previous K tile
        {
            const float4* sh = (const float4*)&g_Kh[(size_t)t * 65536 + (size_t)c * 128 * 128];
            const float4* sl = (const float4*)&g_Kl[(size_t)t * 65536 + (size_t)c * 128 * 128];
            for (int f = tid; f < 2048; f += 512) {
                int row = f >> 4, qd = f & 15;
                *(float4*)&Kh_s[row * QP + qd * 8] = sh[f];
                *(float4*)&Kl_s[row * QP + qd * 8] = sl[f];
            }
        }
        __syncthreads();

        float acc[8][4];
#pragma unroll
        for (int nt = 0; nt < 8; nt++)
#pragma unroll
            for (int e = 0; e < 4; e++) acc[nt][e] = 0.0f;

#pragma unroll 1
        for (int kk = 0; kk < 8; kk++) {
            int ka = kk * 16 + tg * 2;
            uint32_t ah[4], al[4];
            ah[0] = lds_u32(&qh_s[(m0 + g) * QP + ka]);
            ah[1] = lds_u32(&qh_s[(m0 + g + 8) * QP + ka]);
            ah[2] = lds_u32(&qh_s[(m0 + g) * QP + ka + 8]);
            ah[3] = lds_u32(&qh_s[(m0 + g + 8) * QP + ka + 8]);
            al[0] = lds_u32(&ql_s[(m0 + g) * QP + ka]);
            al[1] = lds_u32(&ql_s[(m0 + g + 8) * QP + ka]);
            al[2] = lds_u32(&ql_s[(m0 + g) * QP + ka + 8]);
            al[3] = lds_u32(&ql_s[(m0 + g + 8) * QP + ka + 8]);
#pragma unroll
            for (int nt = 0; nt < 8; nt++) {
                int ib = (ihalf * 64 + nt * 8 + g) * QP + ka;
                uint32_t bh0 = lds_u32(&Kh_s[ib]);
                uint32_t bh1 = lds_u32(&Kh_s[ib + 8]);
                uint32_t bl0 = lds_u32(&Kl_s[ib]);
                uint32_t bl1 = lds_u32(&Kl_s[ib + 8]);
                mma_bf16(acc[nt], ah, bh0, bh1);   // hi*hi
                mma_bf16(acc[nt], ah, bl0, bl1);   // hi*lo
                mma_bf16(acc[nt], al, bh0, bh1);   // lo*hi
            }
        }

        // epilogue for this chunk: tanh(score*inv) * s[i]
#pragma unroll
        for (int nt = 0; nt < 8; nt++) {
            int i0 = c * 128 + ihalf * 64 + nt * 8 + tg * 2;
            float sv0 = s_s[i0], sv1 = s_s[i0 + 1];
            pr0 = fmaf(ftanh(acc[nt][0] * inv), sv0, pr0);
            pr0 = fmaf(ftanh(acc[nt][1] * inv), sv1, pr0);
            pr1 = fmaf(ftanh(acc[nt][2] * inv), sv0, pr1);
            pr1 = fmaf(ftanh(acc[nt][3] * inv), sv1, pr1);
        }
    }

    // reduce over the 4 tg lanes, then across i-halves via smem
    pr0 += __shfl_xor_sync(0xffffffffu, pr0, 1);
    pr0 += __shfl_xor_sync(0xffffffffu, pr0, 2);
    pr1 += __shfl_xor_sync(0xffffffffu, pr1, 1);
    pr1 += __shfl_xor_sync(0xffffffffu, pr1, 2);
    if (tg == 0) {
        part[ihalf * 128 + m0 + g]     = pr0;
        part[ihalf * 128 + m0 + g + 8] = pr1;
    }
    __syncthreads();
    if (tid < 128)
        out[t * 1024 + mt * 128 + tid] = ftanh(part[tid] + part[128 + tid]);
}

// ---------------------------------------------------------------------------
extern "C" void kernel_launch(void* const* d_in, const int* in_sizes, int n_in,
                              void* d_out, int out_size) {
    const float* obs      = (const float*)d_in[0];
    const float* prev_act = (const float*)d_in[1];
    const float* in_shift = (const float*)d_in[2];
    const float* in_scale = (const float*)d_in[3];
    const float* pe       = (const float*)d_in[4];
    const float* W_ih     = (const float*)d_in[5];
    const float* b_ih     = (const float*)d_in[6];
    const float* W_hh     = (const float*)d_in[7];
    const float* b_hh     = (const float*)d_in[8];
    const float* Wq       = (const float*)d_in[9];
    const float* bq       = (const float*)d_in[10];
    const float* Wk       = (const float*)d_in[11];
    const float* bk       = (const float*)d_in[12];
    float* out = (float*)d_out;

    cudaFuncSetAttribute(attn_kernel, cudaFuncAttributeMaxDynamicSharedMemorySize,
                         ATTN_SMEM);
    cudaFuncSetAttribute(lstm_kernel, cudaFuncAttributeMaxDynamicSharedMemorySize,
                         LSTM_SMEM);

    prep_kernel<<<512, 256>>>(obs, prev_act, in_shift, in_scale, W_ih, b_ih, b_hh);
    q_kernel<<<512, 256>>>(pe, Wq, bq);
    lstm_kernel<<<128, 512, LSTM_SMEM>>>(W_hh, Wk, bk);
    dim3 ga(8, 256);
    attn_kernel<<<ga, 512, ATTN_SMEM>>>(out);
}

// round 8
// speedup vs baseline: 1.7221x; 1.0255x over previous
#include <cuda_runtime.h>
#include <cuda_bf16.h>
#include <math.h>
#include <stdint.h>

#define TT 256
#define OBS 512
#define HID 1024
#define MSG 128

typedef unsigned long long u64;

// ---- device scratch (static; no allocations) ----
__device__ __align__(16) __nv_bfloat16 g_qh[HID * MSG];        // q hi  [m][k]
__device__ __align__(16) __nv_bfloat16 g_ql[HID * MSG];        // q lo
__device__ __align__(16) __nv_bfloat16 g_Kh[TT * OBS * MSG];   // K hi  [t][i][k]
__device__ __align__(16) __nv_bfloat16 g_Kl[TT * OBS * MSG];   // K lo
__device__ float g_x[TT * OBS];                                // normalized obs
__device__ float g_act[TT * OBS];                              // b_ih+b_hh + W_ih[:,1:]@a_t
__device__ float g_wih0[512];                                  // W_ih[:,0]

// ---- packed fp32x2 helpers ----
__device__ __forceinline__ u64 ffma2(u64 a, u64 b, u64 c) {
    u64 d; asm("fma.rn.f32x2 %0, %1, %2, %3;" : "=l"(d) : "l"(a), "l"(b), "l"(c));
    return d;
}
__device__ __forceinline__ float2 up2(u64 a) {
    float lo, hi; asm("mov.b64 {%0, %1}, %2;" : "=f"(lo), "=f"(hi) : "l"(a));
    return make_float2(lo, hi);
}

__device__ __forceinline__ float fsig(float x) {
    return 1.0f / (1.0f + __expf(-x));
}
__device__ __forceinline__ float ftanh(float x) {
    float t = __expf(-2.0f * fabsf(x));
    float r = (1.0f - t) / (1.0f + t);
    return copysignf(r, x);
}

// ---------------------------------------------------------------------------
// prep: normalize obs, action term, wih0
// ---------------------------------------------------------------------------
__global__ void prep_kernel(const float* __restrict__ obs,
                            const float* __restrict__ prev_act,
                            const float* __restrict__ in_shift,
                            const float* __restrict__ in_scale,
                            const float* __restrict__ W_ih,
                            const float* __restrict__ b_ih,
                            const float* __restrict__ b_hh) {
    int idx = blockIdx.x * blockDim.x + threadIdx.x;  // 0..131071
    int i = idx & 511;
    int t = idx >> 9;

    g_x[idx] = (obs[idx] - in_shift[i]) / (in_scale[i] + 1e-8f);

    {   // action term per (t, gate j)
        int j = i;
        float a = b_ih[j] + b_hh[j];
        const float* wr = W_ih + j * 33 + 1;
        const float* ar = prev_act + t * 32;
#pragma unroll
        for (int aa = 0; aa < 32; aa++) a = fmaf(wr[aa], ar[aa], a);
        g_act[idx] = a;
    }
    if (idx < 512) g_wih0[idx] = W_ih[idx * 33];
}

// ---------------------------------------------------------------------------
// q = pos_embedding @ Wq^T + bq, stored as bf16 hi/lo pairs [m][k]
// ---------------------------------------------------------------------------
__global__ void q_kernel(const float* __restrict__ pe,
                         const float* __restrict__ Wq,
                         const float* __restrict__ bq) {
    int idx = blockIdx.x * blockDim.x + threadIdx.x;  // 131072
    int m = idx >> 7, j = idx & 127;
    float acc = bq[j];
    const float* per = pe + m * 128;
    const float* wr = Wq + j * 128;
#pragma unroll 4
    for (int k = 0; k < 128; k++) acc = fmaf(per[k], wr[k], acc);

    __nv_bfloat16 hb = __float2bfloat16(acc);
    __nv_bfloat16 lb = __float2bfloat16(acc - __bfloat162float(hb));
    g_qh[idx] = hb;
    g_ql[idx] = lb;
}

// ---------------------------------------------------------------------------
// Fused LSTM: 128 CTAs x 4 neurons, 512 threads, 2 barriers/step.
// Phase A: gates(t) and kmsg(t-1) INTERLEAVED in one unrolled loop —
// two independent dependency chains per scheduling window.
// ---------------------------------------------------------------------------
#define WHH_P 68
#define WK_P 132
#define LSTM_SMEM ((512 * WHH_P + 128 * WK_P + 2048 + 2048 + 512 + 8) * (int)sizeof(float))

__global__ __launch_bounds__(512) void lstm_kernel(const float* __restrict__ W_hh,
                                                   const float* __restrict__ Wk,
                                                   const float* __restrict__ bk) {
    extern __shared__ float sm[];
    float* Whh_s = sm;                         // 512 x WHH_P (k 0..63)
    float* Wk_s  = Whh_s + 512 * WHH_P;        // 128 x WK_P
    float* gt_s  = Wk_s + 128 * WK_P;          // 2048 : [n][512]
    float* kp_s  = gt_s + 2048;                // 2048 : [ks][n][128]
    float* h_s   = kp_s + 2048;                // 512  : [n][128]
    float* s_s   = h_s + 512;                  // 8    : double-buffered s

    int tid = threadIdx.x;                     // 0..511
    int n0 = blockIdx.x * 4;
    int j = tid;
    int ks = tid >> 7, jj = tid & 127;         // kmsg / pointwise mapping

    // --- one-time staging ---
    {   // Whh rows, k 0..63, pitch WHH_P
        const float4* wr = (const float4*)(W_hh + j * 128);
#pragma unroll
        for (int i = 0; i < 16; i++)
            *(float4*)&Whh_s[j * WHH_P + i * 4] = wr[i];
    }
    ulonglong2 wreg[16];   // Whh row j, k 64..127 (register-resident)
    {
        const ulonglong2* wr = (const ulonglong2*)(W_hh + j * 128 + 64);
#pragma unroll
        for (int i = 0; i < 16; i++) wreg[i] = wr[i];
    }
    for (int f = tid; f < 128 * 32; f += 512) {   // Wk rows, pitch WK_P
        int row = f >> 5, q4 = f & 31;
        *(float4*)&Wk_s[row * WK_P + q4 * 4] = *(const float4*)&Wk[row * 128 + q4 * 4];
    }
    h_s[tid] = 0.0f;
    float c_r    = 0.0f;
    float act_r  = g_act[j];
    float wih0_r = g_wih0[j];
    float bk_r   = bk[jj];
    if (tid < 4) s_s[tid] = g_x[n0 + tid];
    __syncthreads();

    for (int t = 0; t < TT; t++) {
        const float* sb = s_s + (t & 1) * 4;

        // ================= Phase A (interleaved gates + kmsg) =============
        u64 a0 = 0, a1 = 0, a2 = 0, a3 = 0;          // gates(t), h(t-1)
        u64 ka0 = 0, ka1 = 0, ka2 = 0, ka3 = 0;      // kmsg(t-1), same h(t-1)

#pragma unroll
        for (int o = 0; o < 8; o++) {
            // --- kmsg slice: k4 = ks*8 + o (runtime base) ---
            {
                int k4 = ks * 8 + o;
                ulonglong2 wv = *(const ulonglong2*)&Wk_s[jj * WK_P + k4 * 4];
                ulonglong2 h0 = *(const ulonglong2*)&h_s[k4 * 4];
                ulonglong2 h1 = *(const ulonglong2*)&h_s[128 + k4 * 4];
                ulonglong2 h2 = *(const ulonglong2*)&h_s[256 + k4 * 4];
                ulonglong2 h3 = *(const ulonglong2*)&h_s[384 + k4 * 4];
                ka0 = ffma2(wv.x, h0.x, ka0); ka0 = ffma2(wv.y, h0.y, ka0);
                ka1 = ffma2(wv.x, h1.x, ka1); ka1 = ffma2(wv.y, h1.y, ka1);
                ka2 = ffma2(wv.x, h2.x, ka2); ka2 = ffma2(wv.y, h2.y, ka2);
                ka3 = ffma2(wv.x, h3.x, ka3); ka3 = ffma2(wv.y, h3.y, ka3);
            }
            // --- gates slices: k4 = 4o .. 4o+3 (compile-time) ---
#pragma unroll
            for (int u = 0; u < 4; u++) {
                int k4 = o * 4 + u;
                ulonglong2 wv;
                if (k4 < 16)
                    wv = *(const ulonglong2*)&Whh_s[j * WHH_P + k4 * 4];
                else
                    wv = wreg[k4 - 16];
                ulonglong2 h0 = *(const ulonglong2*)&h_s[k4 * 4];
                ulonglong2 h1 = *(const ulonglong2*)&h_s[128 + k4 * 4];
                ulonglong2 h2 = *(const ulonglong2*)&h_s[256 + k4 * 4];
                ulonglong2 h3 = *(const ulonglong2*)&h_s[384 + k4 * 4];
                a0 = ffma2(wv.x, h0.x, a0); a0 = ffma2(wv.y, h0.y, a0);
                a1 = ffma2(wv.x, h1.x, a1); a1 = ffma2(wv.y, h1.y, a1);
                a2 = ffma2(wv.x, h2.x, a2); a2 = ffma2(wv.y, h2.y, a2);
                a3 = ffma2(wv.x, h3.x, a3); a3 = ffma2(wv.y, h3.y, a3);
            }
        }
        {
            float base = act_r;
            float2 v0 = up2(a0), v1 = up2(a1), v2 = up2(a2), v3 = up2(a3);
            gt_s[0 * 512 + j] = v0.x + v0.y + fmaf(sb[0], wih0_r, base);
            gt_s[1 * 512 + j] = v1.x + v1.y + fmaf(sb[1], wih0_r, base);
            gt_s[2 * 512 + j] = v2.x + v2.y + fmaf(sb[2], wih0_r, base);
            gt_s[3 * 512 + j] = v3.x + v3.y + fmaf(sb[3], wih0_r, base);
            float2 k0 = up2(ka0), k1 = up2(ka1), k2 = up2(ka2), k3 = up2(ka3);
            kp_s[ks * 512 + 0 * 128 + jj] = k0.x + k0.y;
            kp_s[ks * 512 + 1 * 128 + jj] = k1.x + k1.y;
            kp_s[ks * 512 + 2 * 128 + jj] = k2.x + k2.y;
            kp_s[ks * 512 + 3 * 128 + jj] = k3.x + k3.y;
        }
        __syncthreads();

        // ================= Phase B =================
        if (t > 0) {   // kmsg reduce + store for step t-1 (ks == n here)
            float acc = bk_r
                      + kp_s[ks * 128 + jj]        + kp_s[512 + ks * 128 + jj]
                      + kp_s[1024 + ks * 128 + jj] + kp_s[1536 + ks * 128 + jj];
            __nv_bfloat16 hb = __float2bfloat16(acc);
            __nv_bfloat16 lb = __float2bfloat16(acc - __bfloat162float(hb));
            size_t off = (size_t)(t - 1) * 65536 + (size_t)(n0 + ks) * 128 + jj;
            g_Kh[off] = hb;
            g_Kl[off] = lb;
        }
        // pointwise(t): gt_s -> h_s (torch gate order i,f,g,o)
        {
            float ig = gt_s[ks * 512 + jj];
            float fg = gt_s[ks * 512 + 128 + jj];
            float gg = gt_s[ks * 512 + 256 + jj];
            float og = gt_s[ks * 512 + 384 + jj];
            float c = fsig(fg) * c_r + fsig(ig) * ftanh(gg);
            float h = fsig(og) * ftanh(c);
            c_r = c;
            h_s[ks * 128 + jj] = h;
        }
        // prefetch next-step inputs
        {
            int tn = (t + 1 < TT) ? t + 1 : t;
            if (tid < 4) s_s[((t + 1) & 1) * 4 + tid] = g_x[tn * 512 + n0 + tid];
            act_r = g_act[tn * 512 + j];
        }
        __syncthreads();
    }

    // ---- tail: kmsg for step 255 (h_s holds h(255)) ----
    {
        u64 ka0 = 0, ka1 = 0, ka2 = 0, ka3 = 0;
#pragma unroll
        for (int k4i = 0; k4i < 8; k4i++) {
            int k4 = ks * 8 + k4i;
            ulonglong2 wv = *(const ulonglong2*)&Wk_s[jj * WK_P + k4 * 4];
            ulonglong2 h0 = *(const ulonglong2*)&h_s[k4 * 4];
            ulonglong2 h1 = *(const ulonglong2*)&h_s[128 + k4 * 4];
            ulonglong2 h2 = *(const ulonglong2*)&h_s[256 + k4 * 4];
            ulonglong2 h3 = *(const ulonglong2*)&h_s[384 + k4 * 4];
            ka0 = ffma2(wv.x, h0.x, ka0); ka0 = ffma2(wv.y, h0.y, ka0);
            ka1 = ffma2(wv.x, h1.x, ka1); ka1 = ffma2(wv.y, h1.y, ka1);
            ka2 = ffma2(wv.x, h2.x, ka2); ka2 = ffma2(wv.y, h2.y, ka2);
            ka3 = ffma2(wv.x, h3.x, ka3); ka3 = ffma2(wv.y, h3.y, ka3);
        }
        float2 v0 = up2(ka0), v1 = up2(ka1), v2 = up2(ka2), v3 = up2(ka3);
        kp_s[ks * 512 + 0 * 128 + jj] = v0.x + v0.y;
        kp_s[ks * 512 + 1 * 128 + jj] = v1.x + v1.y;
        kp_s[ks * 512 + 2 * 128 + jj] = v2.x + v2.y;
        kp_s[ks * 512 + 3 * 128 + jj] = v3.x + v3.y;
    }
    __syncthreads();
    {
        float acc = bk_r
                  + kp_s[ks * 128 + jj]        + kp_s[512 + ks * 128 + jj]
                  + kp_s[1024 + ks * 128 + jj] + kp_s[1536 + ks * 128 + jj];
        __nv_bfloat16 hb = __float2bfloat16(acc);
        __nv_bfloat16 lb = __float2bfloat16(acc - __bfloat162float(hb));
        size_t off = (size_t)255 * 65536 + (size_t)(n0 + ks) * 128 + jj;
        g_Kh[off] = hb;
        g_Kl[off] = lb;
    }
}

// ---------------------------------------------------------------------------
// Phase B via mma.sync m16n8k16 bf16 (hi/lo split, fp32 accumulate).
// CTA = 64 m x 512 i (grid 16 x 256) -> ~108 KB smem -> 2 CTAs/SM.
// warp = (m-band 0..3, i-quarter 0..3); 4 n-tiles per warp per chunk.
// ---------------------------------------------------------------------------
#define QP 136   // smem row pitch (bf16) -> conflict-free 32-bit fragment loads
#define QTILE (64 * QP)
#define KTILE (128 * QP)
#define ATTN_SMEM ((2 * QTILE + 2 * KTILE) * 2 + 512 * 4 + 256 * 4 + 128)

__device__ __forceinline__ uint32_t lds_u32(const __nv_bfloat16* p) {
    return *(const uint32_t*)p;
}

__device__ __forceinline__ void mma_bf16(float* d, const uint32_t* a,
                                         uint32_t b0, uint32_t b1) {
    asm volatile(
        "mma.sync.aligned.m16n8k16.row.col.f32.bf16.bf16.f32 "
        "{%0,%1,%2,%3}, {%4,%5,%6,%7}, {%8,%9}, {%0,%1,%2,%3};"
        : "+f"(d[0]), "+f"(d[1]), "+f"(d[2]), "+f"(d[3])
        : "r"(a[0]), "r"(a[1]), "r"(a[2]), "r"(a[3]), "r"(b0), "r"(b1));
}

__global__ __launch_bounds__(512) void attn_kernel(float* __restrict__ out) {
    extern __shared__ char smc[];
    __nv_bfloat16* qh_s = (__nv_bfloat16*)smc;        // 64 x QP
    __nv_bfloat16* ql_s = qh_s + QTILE;
    __nv_bfloat16* Kh_s = ql_s + QTILE;               // 128 x QP
    __nv_bfloat16* Kl_s = Kh_s + KTILE;
    float* s_s  = (float*)(Kl_s + KTILE);             // 512 floats
    float* part = s_s + 512;                          // 256 floats

    int tid = threadIdx.x;
    int warp = tid >> 5;
    int lane = tid & 31;
    int wband = warp >> 2;   // 0..3 : m band (16 rows)
    int iq    = warp & 3;    // 0..3 : i quarter (32 i) within chunk
    int g  = lane >> 2;      // 0..7
    int tg = lane & 3;       // 0..3
    int m0 = wband * 16;
    int mq = blockIdx.x;     // 0..15 (64 m rows each)
    int t  = blockIdx.y;     // 0..255

    // stage q tile (hi/lo) with pitch QP
    {
        const float4* sh = (const float4*)&g_qh[(size_t)mq * 64 * 128];
        const float4* sl = (const float4*)&g_ql[(size_t)mq * 64 * 128];
        for (int f = tid; f < 1024; f += 512) {
            int row = f >> 4, qd = f & 15;
            *(float4*)&qh_s[row * QP + qd * 8] = sh[f];
            *(float4*)&ql_s[row * QP + qd * 8] = sl[f];
        }
        const float4* sx = (const float4*)&g_x[t * 512];
        if (tid < 128) ((float4*)s_s)[tid] = sx[tid];
    }

    float pr0 = 0.0f, pr1 = 0.0f;   // partials for rows m0+g, m0+g+8
    const float inv = 0.0883883476483184f;  // 1/sqrt(128)

#pragma unroll 1
    for (int c = 0; c < 4; c++) {
        if (c > 0) __syncthreads();   // everyone done with previous K tile
        {
            const float4* sh = (const float4*)&g_Kh[(size_t)t * 65536 + (size_t)c * 128 * 128];
            const float4* sl = (const float4*)&g_Kl[(size_t)t * 65536 + (size_t)c * 128 * 128];
            for (int f = tid; f < 2048; f += 512) {
                int row = f >> 4, qd = f & 15;
                *(float4*)&Kh_s[row * QP + qd * 8] = sh[f];
                *(float4*)&Kl_s[row * QP + qd * 8] = sl[f];
            }
        }
        __syncthreads();

        float acc[4][4];
#pragma unroll
        for (int nt = 0; nt < 4; nt++)
#pragma unroll
            for (int e = 0; e < 4; e++) acc[nt][e] = 0.0f;

#pragma unroll 1
        for (int kk = 0; kk < 8; kk++) {
            int ka = kk * 16 + tg * 2;
            uint32_t ah[4], al[4];
            ah[0] = lds_u32(&qh_s[(m0 + g) * QP + ka]);
            ah[1] = lds_u32(&qh_s[(m0 + g + 8) * QP + ka]);
            ah[2] = lds_u32(&qh_s[(m0 + g) * QP + ka + 8]);
            ah[3] = lds_u32(&qh_s[(m0 + g + 8) * QP + ka + 8]);
            al[0] = lds_u32(&ql_s[(m0 + g) * QP + ka]);
            al[1] = lds_u32(&ql_s[(m0 + g + 8) * QP + ka]);
            al[2] = lds_u32(&ql_s[(m0 + g) * QP + ka + 8]);
            al[3] = lds_u32(&ql_s[(m0 + g + 8) * QP + ka + 8]);
#pragma unroll
            for (int nt = 0; nt < 4; nt++) {
                int ib = (iq * 32 + nt * 8 + g) * QP + ka;
                uint32_t bh0 = lds_u32(&Kh_s[ib]);
                uint32_t bh1 = lds_u32(&Kh_s[ib + 8]);
                uint32_t bl0 = lds_u32(&Kl_s[ib]);
                uint32_t bl1 = lds_u32(&Kl_s[ib + 8]);
                mma_bf16(acc[nt], ah, bh0, bh1);   // hi*hi
                mma_bf16(acc[nt], ah, bl0, bl1);   // hi*lo
                mma_bf16(acc[nt], al, bh0, bh1);   // lo*hi
            }
        }

        // epilogue for this chunk: tanh(score*inv) * s[i]
#pragma unroll
        for (int nt = 0; nt < 4; nt++) {
            int i0 = c * 128 + iq * 32 + nt * 8 + tg * 2;
            float sv0 = s_s[i0], sv1 = s_s[i0 + 1];
            pr0 = fmaf(ftanh(acc[nt][0] * inv), sv0, pr0);
            pr0 = fmaf(ftanh(acc[nt][1] * inv), sv1, pr0);
            pr1 = fmaf(ftanh(acc[nt][2] * inv), sv0, pr1);
            pr1 = fmaf(ftanh(acc[nt][3] * inv), sv1, pr1);
        }
    }

    // reduce over the 4 tg lanes, then across i-quarters via smem
    pr0 += __shfl_xor_sync(0xffffffffu, pr0, 1);
    pr0 += __shfl_xor_sync(0xffffffffu, pr0, 2);
    pr1 += __shfl_xor_sync(0xffffffffu, pr1, 1);
    pr1 += __shfl_xor_sync(0xffffffffu, pr1, 2);
    if (tg == 0) {
        part[iq * 64 + m0 + g]     = pr0;
        part[iq * 64 + m0 + g + 8] = pr1;
    }
    __syncthreads();
    if (tid < 64)
        out[t * 1024 + mq * 64 + tid] =
            ftanh(part[tid] + part[64 + tid] + part[128 + tid] + part[192 + tid]);
}

// ---------------------------------------------------------------------------
extern "C" void kernel_launch(void* const* d_in, const int* in_sizes, int n_in,
                              void* d_out, int out_size) {
    const float* obs      = (const float*)d_in[0];
    const float* prev_act = (const float*)d_in[1];
    const float* in_shift = (const float*)d_in[2];
    const float* in_scale = (const float*)d_in[3];
    const float* pe       = (const float*)d_in[4];
    const float* W_ih     = (const float*)d_in[5];
    const float* b_ih     = (const float*)d_in[6];
    const float* W_hh     = (const float*)d_in[7];
    const float* b_hh     = (const float*)d_in[8];
    const float* Wq       = (const float*)d_in[9];
    const float* bq       = (const float*)d_in[10];
    const float* Wk       = (const float*)d_in[11];
    const float* bk       = (const float*)d_in[12];
    float* out = (float*)d_out;

    cudaFuncSetAttribute(attn_kernel, cudaFuncAttributeMaxDynamicSharedMemorySize,
                         ATTN_SMEM);
    cudaFuncSetAttribute(lstm_kernel, cudaFuncAttributeMaxDynamicSharedMemorySize,
                         LSTM_SMEM);

    prep_kernel<<<512, 256>>>(obs, prev_act, in_shift, in_scale, W_ih, b_ih, b_hh);
    q_kernel<<<512, 256>>>(pe, Wq, bq);
    lstm_kernel<<<128, 512, LSTM_SMEM>>>(W_hh, Wk, bk);
    dim3 ga(16, 256);
    attn_kernel<<<ga, 512, ATTN_SMEM>>>(out);
}

// round 9
// speedup vs baseline: 1.8233x; 1.0588x over previous
#include <cuda_runtime.h>
#include <cuda_bf16.h>
#include <math.h>
#include <stdint.h>

#define TT 256
#define OBS 512
#define HID 1024
#define MSG 128

typedef unsigned long long u64;

// ---- device scratch (static; no allocations) ----
__device__ __align__(16) __nv_bfloat16 g_qh[HID * MSG];        // q' hi [m][p]
__device__ __align__(16) __nv_bfloat16 g_ql[HID * MSG];        // q' lo
__device__ __align__(16) __nv_bfloat16 g_Kh[TT * OBS * MSG];   // h hi  [t][i][p]
__device__ __align__(16) __nv_bfloat16 g_Kl[TT * OBS * MSG];   // h lo
__device__ float g_qf[HID * MSG];                              // q fp32 [m][j]
__device__ float g_c[HID];                                     // c[m] = q[m].bk
__device__ float g_x[TT * OBS];                                // normalized obs
__device__ float g_act[TT * OBS];                              // b_ih+b_hh + W_ih[:,1:]@a_t
__device__ float g_wih0[512];                                  // W_ih[:,0]

// ---- packed fp32x2 helpers ----
__device__ __forceinline__ u64 ffma2(u64 a, u64 b, u64 c) {
    u64 d; asm("fma.rn.f32x2 %0, %1, %2, %3;" : "=l"(d) : "l"(a), "l"(b), "l"(c));
    return d;
}
__device__ __forceinline__ float2 up2(u64 a) {
    float lo, hi; asm("mov.b64 {%0, %1}, %2;" : "=f"(lo), "=f"(hi) : "l"(a));
    return make_float2(lo, hi);
}

__device__ __forceinline__ float fsig(float x) {
    return 1.0f / (1.0f + __expf(-x));
}
__device__ __forceinline__ float ftanh(float x) {
    float t = __expf(-2.0f * fabsf(x));
    float r = (1.0f - t) / (1.0f + t);
    return copysignf(r, x);
}

// ---------------------------------------------------------------------------
// prep: normalize obs, action term, wih0
// ---------------------------------------------------------------------------
__global__ void prep_kernel(const float* __restrict__ obs,
                            const float* __restrict__ prev_act,
                            const float* __restrict__ in_shift,
                            const float* __restrict__ in_scale,
                            const float* __restrict__ W_ih,
                            const float* __restrict__ b_ih,
                            const float* __restrict__ b_hh) {
    int idx = blockIdx.x * blockDim.x + threadIdx.x;  // 0..131071
    int i = idx & 511;
    int t = idx >> 9;

    g_x[idx] = (obs[idx] - in_shift[i]) / (in_scale[i] + 1e-8f);

    {   // action term per (t, gate j)
        int j = i;
        float a = b_ih[j] + b_hh[j];
        const float* wr = W_ih + j * 33 + 1;
        const float* ar = prev_act + t * 32;
#pragma unroll
        for (int aa = 0; aa < 32; aa++) a = fmaf(wr[aa], ar[aa], a);
        g_act[idx] = a;
    }
    if (idx < 512) g_wih0[idx] = W_ih[idx * 33];
}

// ---------------------------------------------------------------------------
// q1: q = pos_embedding @ Wq^T + bq  (fp32, [m][j])
// ---------------------------------------------------------------------------
__global__ void q1_kernel(const float* __restrict__ pe,
                          const float* __restrict__ Wq,
                          const float* __restrict__ bq) {
    int idx = blockIdx.x * blockDim.x + threadIdx.x;  // 131072
    int m = idx >> 7, j = idx & 127;
    float acc = bq[j];
    const float* per = pe + m * 128;
    const float* wr = Wq + j * 128;
#pragma unroll 4
    for (int k = 0; k < 128; k++) acc = fmaf(per[k], wr[k], acc);
    g_qf[idx] = acc;
}

// ---------------------------------------------------------------------------
// q2: q'[m][p] = sum_j q[m][j] * Wk[j][p]  (hi/lo bf16), c[m] = q[m].bk
// ---------------------------------------------------------------------------
__global__ void q2_kernel(const float* __restrict__ Wk,
                          const float* __restrict__ bk) {
    int idx = blockIdx.x * blockDim.x + threadIdx.x;  // 131072
    int m = idx >> 7, p = idx & 127;
    const float* qf = g_qf + m * 128;
    float acc = 0.0f;
#pragma unroll 4
    for (int j = 0; j < 128; j++) acc = fmaf(qf[j], Wk[j * 128 + p], acc);

    __nv_bfloat16 hb = __float2bfloat16(acc);
    __nv_bfloat16 lb = __float2bfloat16(acc - __bfloat162float(hb));
    g_qh[idx] = hb;
    g_ql[idx] = lb;

    if (p == 0) {
        float c = 0.0f;
#pragma unroll 4
        for (int j = 0; j < 128; j++) c = fmaf(qf[j], bk[j], c);
        g_c[m] = c;
    }
}

// ---------------------------------------------------------------------------
// LSTM (gates only — kmsg algebraically eliminated): 128 CTAs x 4 neurons,
// 512 threads, 2 barriers/step. Whh: 24 k4-chunks smem + 8 in registers.
// Stores h as bf16 hi/lo [t][i][p].
// ---------------------------------------------------------------------------
#define WHH_P 100
#define LSTM_SMEM ((512 * WHH_P + 2048 + 512 + 8) * (int)sizeof(float))

__global__ __launch_bounds__(512) void lstm_kernel(const float* __restrict__ W_hh) {
    extern __shared__ float sm[];
    float* Whh_s = sm;                         // 512 x WHH_P (k4 0..23)
    float* gt_s  = Whh_s + 512 * WHH_P;        // 2048 : [n][512]
    float* h_s   = gt_s + 2048;                // 512  : [n][128]
    float* s_s   = h_s + 512;                  // 8    : double-buffered s

    int tid = threadIdx.x;                     // 0..511
    int n0 = blockIdx.x * 4;
    int j = tid;
    int ks = tid >> 7, jj = tid & 127;         // pointwise/store mapping

    // --- one-time staging ---
    {   // Whh rows, k 0..95, pitch WHH_P (conflict-free LDS.128)
        const float4* wr = (const float4*)(W_hh + j * 128);
#pragma unroll
        for (int i = 0; i < 24; i++)
            *(float4*)&Whh_s[j * WHH_P + i * 4] = wr[i];
    }
    ulonglong2 wreg[8];   // Whh row j, k 96..127 (register-resident)
    {
        const ulonglong2* wr = (const ulonglong2*)(W_hh + j * 128 + 96);
#pragma unroll
        for (int i = 0; i < 8; i++) wreg[i] = wr[i];
    }
    h_s[tid] = 0.0f;
    float c_r    = 0.0f;
    float act_r  = g_act[j];
    float wih0_r = g_wih0[j];
    if (tid < 4) s_s[tid] = g_x[n0 + tid];
    __syncthreads();

    for (int t = 0; t < TT; t++) {
        const float* sb = s_s + (t & 1) * 4;

        // ---- gates(t): thread = column j, 4 neurons, k-pair packed ----
        u64 a0 = 0, a1 = 0, a2 = 0, a3 = 0;
#pragma unroll
        for (int k4 = 0; k4 < 24; k4++) {   // smem W chunks
            ulonglong2 wv = *(const ulonglong2*)&Whh_s[j * WHH_P + k4 * 4];
            ulonglong2 h0 = *(const ulonglong2*)&h_s[k4 * 4];
            ulonglong2 h1 = *(const ulonglong2*)&h_s[128 + k4 * 4];
            ulonglong2 h2 = *(const ulonglong2*)&h_s[256 + k4 * 4];
            ulonglong2 h3 = *(const ulonglong2*)&h_s[384 + k4 * 4];
            a0 = ffma2(wv.x, h0.x, a0); a0 = ffma2(wv.y, h0.y, a0);
            a1 = ffma2(wv.x, h1.x, a1); a1 = ffma2(wv.y, h1.y, a1);
            a2 = ffma2(wv.x, h2.x, a2); a2 = ffma2(wv.y, h2.y, a2);
            a3 = ffma2(wv.x, h3.x, a3); a3 = ffma2(wv.y, h3.y, a3);
        }
#pragma unroll
        for (int k4 = 24; k4 < 32; k4++) {  // register W chunks
            ulonglong2 wv = wreg[k4 - 24];
            ulonglong2 h0 = *(const ulonglong2*)&h_s[k4 * 4];
            ulonglong2 h1 = *(const ulonglong2*)&h_s[128 + k4 * 4];
            ulonglong2 h2 = *(const ulonglong2*)&h_s[256 + k4 * 4];
            ulonglong2 h3 = *(const ulonglong2*)&h_s[384 + k4 * 4];
            a0 = ffma2(wv.x, h0.x, a0); a0 = ffma2(wv.y, h0.y, a0);
            a1 = ffma2(wv.x, h1.x, a1); a1 = ffma2(wv.y, h1.y, a1);
            a2 = ffma2(wv.x, h2.x, a2); a2 = ffma2(wv.y, h2.y, a2);
            a3 = ffma2(wv.x, h3.x, a3); a3 = ffma2(wv.y, h3.y, a3);
        }
        {
            float base = act_r;
            float2 v0 = up2(a0), v1 = up2(a1), v2 = up2(a2), v3 = up2(a3);
            gt_s[0 * 512 + j] = v0.x + v0.y + fmaf(sb[0], wih0_r, base);
            gt_s[1 * 512 + j] = v1.x + v1.y + fmaf(sb[1], wih0_r, base);
            gt_s[2 * 512 + j] = v2.x + v2.y + fmaf(sb[2], wih0_r, base);
            gt_s[3 * 512 + j] = v3.x + v3.y + fmaf(sb[3], wih0_r, base);
        }
        __syncthreads();

        // ---- pointwise(t) (torch gate order i,f,g,o) + h store ----
        {
            float ig = gt_s[ks * 512 + jj];
            float fg = gt_s[ks * 512 + 128 + jj];
            float gg = gt_s[ks * 512 + 256 + jj];
            float og = gt_s[ks * 512 + 384 + jj];
            float c = fsig(fg) * c_r + fsig(ig) * ftanh(gg);
            float h = fsig(og) * ftanh(c);
            c_r = c;
            h_s[ks * 128 + jj] = h;
            __nv_bfloat16 hb = __float2bfloat16(h);
            __nv_bfloat16 lb = __float2bfloat16(h - __bfloat162float(hb));
            size_t off = (size_t)t * 65536 + (size_t)(n0 + ks) * 128 + jj;
            g_Kh[off] = hb;
            g_Kl[off] = lb;
        }
        // prefetch next-step inputs
        {
            int tn = (t + 1 < TT) ? t + 1 : t;
            if (tid < 4) s_s[((t + 1) & 1) * 4 + tid] = g_x[tn * 512 + n0 + tid];
            act_r = g_act[tn * 512 + j];
        }
        __syncthreads();
    }
}

// ---------------------------------------------------------------------------
// Attention via mma.sync m16n8k16 bf16 (hi/lo split, fp32 accumulate).
// score[m,i] = q'[m].h[t,i] + c[m];  out[t,m] = tanh(sum_i tanh(score*inv)*s)
// CTA = 64 m x 512 i (grid 16 x 256) -> 2 CTAs/SM.
// ---------------------------------------------------------------------------
#define QP 136   // smem row pitch (bf16) -> conflict-free 32-bit fragment loads
#define QTILE (64 * QP)
#define KTILE (128 * QP)
#define ATTN_SMEM ((2 * QTILE + 2 * KTILE) * 2 + 512 * 4 + 256 * 4 + 128)

__device__ __forceinline__ uint32_t lds_u32(const __nv_bfloat16* p) {
    return *(const uint32_t*)p;
}

__device__ __forceinline__ void mma_bf16(float* d, const uint32_t* a,
                                         uint32_t b0, uint32_t b1) {
    asm volatile(
        "mma.sync.aligned.m16n8k16.row.col.f32.bf16.bf16.f32 "
        "{%0,%1,%2,%3}, {%4,%5,%6,%7}, {%8,%9}, {%0,%1,%2,%3};"
        : "+f"(d[0]), "+f"(d[1]), "+f"(d[2]), "+f"(d[3])
        : "r"(a[0]), "r"(a[1]), "r"(a[2]), "r"(a[3]), "r"(b0), "r"(b1));
}

__global__ __launch_bounds__(512) void attn_kernel(float* __restrict__ out) {
    extern __shared__ char smc[];
    __nv_bfloat16* qh_s = (__nv_bfloat16*)smc;        // 64 x QP
    __nv_bfloat16* ql_s = qh_s + QTILE;
    __nv_bfloat16* Kh_s = ql_s + QTILE;               // 128 x QP
    __nv_bfloat16* Kl_s = Kh_s + KTILE;
    float* s_s  = (float*)(Kl_s + KTILE);             // 512 floats
    float* part = s_s + 512;                          // 256 floats

    int tid = threadIdx.x;
    int warp = tid >> 5;
    int lane = tid & 31;
    int wband = warp >> 2;   // 0..3 : m band (16 rows)
    int iq    = warp & 3;    // 0..3 : i quarter (32 i) within chunk
    int g  = lane >> 2;      // 0..7
    int tg = lane & 3;       // 0..3
    int m0 = wband * 16;
    int mq = blockIdx.x;     // 0..15 (64 m rows each)
    int t  = blockIdx.y;     // 0..255

    // per-thread score constants c[m] for rows m0+g, m0+g+8
    float c0 = g_c[mq * 64 + m0 + g];
    float c1 = g_c[mq * 64 + m0 + g + 8];

    // stage q' tile (hi/lo) with pitch QP
    {
        const float4* sh = (const float4*)&g_qh[(size_t)mq * 64 * 128];
        const float4* sl = (const float4*)&g_ql[(size_t)mq * 64 * 128];
        for (int f = tid; f < 1024; f += 512) {
            int row = f >> 4, qd = f & 15;
            *(float4*)&qh_s[row * QP + qd * 8] = sh[f];
            *(float4*)&ql_s[row * QP + qd * 8] = sl[f];
        }
        const float4* sx = (const float4*)&g_x[t * 512];
        if (tid < 128) ((float4*)s_s)[tid] = sx[tid];
    }

    float pr0 = 0.0f, pr1 = 0.0f;   // partials for rows m0+g, m0+g+8
    const float inv = 0.0883883476483184f;  // 1/sqrt(128)

#pragma unroll 1
    for (int c = 0; c < 4; c++) {
        if (c > 0) __syncthreads();   // everyone done with previous h tile
        {
            const float4* sh = (const float4*)&g_Kh[(size_t)t * 65536 + (size_t)c * 128 * 128];
            const float4* sl = (const float4*)&g_Kl[(size_t)t * 65536 + (size_t)c * 128 * 128];
            for (int f = tid; f < 2048; f += 512) {
                int row = f >> 4, qd = f & 15;
                *(float4*)&Kh_s[row * QP + qd * 8] = sh[f];
                *(float4*)&Kl_s[row * QP + qd * 8] = sl[f];
            }
        }
        __syncthreads();

        float acc[4][4];
#pragma unroll
        for (int nt = 0; nt < 4; nt++)
#pragma unroll
            for (int e = 0; e < 4; e++) acc[nt][e] = 0.0f;

#pragma unroll 1
        for (int kk = 0; kk < 8; kk++) {
            int ka = kk * 16 + tg * 2;
            uint32_t ah[4], al[4];
            ah[0] = lds_u32(&qh_s[(m0 + g) * QP + ka]);
            ah[1] = lds_u32(&qh_s[(m0 + g + 8) * QP + ka]);
            ah[2] = lds_u32(&qh_s[(m0 + g) * QP + ka + 8]);
            ah[3] = lds_u32(&qh_s[(m0 + g + 8) * QP + ka + 8]);
            al[0] = lds_u32(&ql_s[(m0 + g) * QP + ka]);
            al[1] = lds_u32(&ql_s[(m0 + g + 8) * QP + ka]);
            al[2] = lds_u32(&ql_s[(m0 + g) * QP + ka + 8]);
            al[3] = lds_u32(&ql_s[(m0 + g + 8) * QP + ka + 8]);
#pragma unroll
            for (int nt = 0; nt < 4; nt++) {
                int ib = (iq * 32 + nt * 8 + g) * QP + ka;
                uint32_t bh0 = lds_u32(&Kh_s[ib]);
                uint32_t bh1 = lds_u32(&Kh_s[ib + 8]);
                uint32_t bl0 = lds_u32(&Kl_s[ib]);
                uint32_t bl1 = lds_u32(&Kl_s[ib + 8]);
                mma_bf16(acc[nt], ah, bh0, bh1);   // hi*hi
                mma_bf16(acc[nt], ah, bl0, bl1);   // hi*lo
                mma_bf16(acc[nt], al, bh0, bh1);   // lo*hi
            }
        }

        // epilogue for this chunk: tanh((score + c[m]) * inv) * s[i]
#pragma unroll
        for (int nt = 0; nt < 4; nt++) {
            int i0 = c * 128 + iq * 32 + nt * 8 + tg * 2;
            float sv0 = s_s[i0], sv1 = s_s[i0 + 1];
            pr0 = fmaf(ftanh((acc[nt][0] + c0) * inv), sv0, pr0);
            pr0 = fmaf(ftanh((acc[nt][1] + c0) * inv), sv1, pr0);
            pr1 = fmaf(ftanh((acc[nt][2] + c1) * inv), sv0, pr1);
            pr1 = fmaf(ftanh((acc[nt][3] + c1) * inv), sv1, pr1);
        }
    }

    // reduce over the 4 tg lanes, then across i-quarters via smem
    pr0 += __shfl_xor_sync(0xffffffffu, pr0, 1);
    pr0 += __shfl_xor_sync(0xffffffffu, pr0, 2);
    pr1 += __shfl_xor_sync(0xffffffffu, pr1, 1);
    pr1 += __shfl_xor_sync(0xffffffffu, pr1, 2);
    if (tg == 0) {
        part[iq * 64 + m0 + g]     = pr0;
        part[iq * 64 + m0 + g + 8] = pr1;
    }
    __syncthreads();
    if (tid < 64)
        out[t * 1024 + mq * 64 + tid] =
            ftanh(part[tid] + part[64 + tid] + part[128 + tid] + part[192 + tid]);
}

// ---------------------------------------------------------------------------
extern "C" void kernel_launch(void* const* d_in, const int* in_sizes, int n_in,
                              void* d_out, int out_size) {
    const float* obs      = (const float*)d_in[0];
    const float* prev_act = (const float*)d_in[1];
    const float* in_shift = (const float*)d_in[2];
    const float* in_scale = (const float*)d_in[3];
    const float* pe       = (const float*)d_in[4];
    const float* W_ih     = (const float*)d_in[5];
    const float* b_ih     = (const float*)d_in[6];
    const float* W_hh     = (const float*)d_in[7];
    const float* b_hh     = (const float*)d_in[8];
    const float* Wq       = (const float*)d_in[9];
    const float* bq       = (const float*)d_in[10];
    const float* Wk       = (const float*)d_in[11];
    const float* bk       = (const float*)d_in[12];
    float* out = (float*)d_out;

    cudaFuncSetAttribute(attn_kernel, cudaFuncAttributeMaxDynamicSharedMemorySize,
                         ATTN_SMEM);
    cudaFuncSetAttribute(lstm_kernel, cudaFuncAttributeMaxDynamicSharedMemorySize,
                         LSTM_SMEM);

    prep_kernel<<<512, 256>>>(obs, prev_act, in_shift, in_scale, W_ih, b_ih, b_hh);
    q1_kernel<<<512, 256>>>(pe, Wq, bq);
    q2_kernel<<<512, 256>>>(Wk, bk);
    lstm_kernel<<<128, 512, LSTM_SMEM>>>(W_hh);
    dim3 ga(16, 256);
    attn_kernel<<<ga, 512, ATTN_SMEM>>>(out);
}